// round 9
// baseline (speedup 1.0000x reference)
#include <cuda_runtime.h>
#include <cuda_bf16.h>
#include <cuda_fp16.h>
#include <math.h>
#include <stdint.h>

#define S  2048
#define H  1024
#define NH 16
#define DH 64
#define FF 4096
#define NLAYERS 6
#define VPAD 50432     // 50257 padded to multiple of 128

#define SZ_SH (S*H)

// ---------------- device scratch ----------------
__device__ __align__(16) float g_x[SZ_SH];
__device__ __align__(16) float g_tmp[SZ_SH];
__device__ __align__(16) float g_res[SZ_SH];
__device__ __align__(16) float g_qkv[S*3072];
__device__ __align__(16) float g_suf[SZ_SH];
__device__ __align__(16) float g_m[8*NH*DH*DH];     // split-K partials
__device__ __align__(16) float g_part[16*1024];
__device__ __align__(16) float g_zb[8192];          // zero bias (never written)

// activation hi/lo
__device__ __align__(128) __nv_bfloat16 g_ahi[S*FF];
__device__ __align__(128) __nv_bfloat16 g_alo[S*FF];
__device__ __align__(128) __nv_bfloat16 g_bhi[S*FF];
__device__ __align__(128) __nv_bfloat16 g_blo[S*FF];

// weight hi/lo, K-major transposed [N,K]
__device__ __align__(128) __nv_bfloat16 g_btqkv_hi[NLAYERS*3072*H];
__device__ __align__(128) __nv_bfloat16 g_btqkv_lo[NLAYERS*3072*H];
__device__ __align__(128) __nv_bfloat16 g_btp_hi[NLAYERS*H*H];
__device__ __align__(128) __nv_bfloat16 g_btp_lo[NLAYERS*H*H];
__device__ __align__(128) __nv_bfloat16 g_bt1_hi[NLAYERS*H*FF];
__device__ __align__(128) __nv_bfloat16 g_bt1_lo[NLAYERS*H*FF];
__device__ __align__(128) __nv_bfloat16 g_bt2_hi[NLAYERS*H*FF];
__device__ __align__(128) __nv_bfloat16 g_bt2_lo[NLAYERS*H*FF];
__device__ __align__(128) __half g_wlm_f16[VPAD*H];  // fp16 LM weights, pad rows stay zero
__device__ __align__(128) __half g_xf_f16[SZ_SH];    // fp16 final-LN activations

// ---------------- PTX helpers ----------------
__device__ __forceinline__ uint32_t smem_u32(const void* p) {
    uint32_t a;
    asm("{ .reg .u64 t; cvta.to.shared.u64 t, %1; cvt.u32.u64 %0, t; }" : "=r"(a) : "l"(p));
    return a;
}
__device__ __forceinline__ void cp16(uint32_t dst, const void* src) {
    asm volatile("cp.async.cg.shared.global [%0], [%1], 16;" :: "r"(dst), "l"(src));
}
__device__ __forceinline__ void cp_commit() { asm volatile("cp.async.commit_group;" ::: "memory"); }
template<int N> __device__ __forceinline__ void cp_wait() {
    asm volatile("cp.async.wait_group %0;" :: "n"(N) : "memory");
}
__device__ __forceinline__ void ldsm4(uint32_t& r0, uint32_t& r1, uint32_t& r2, uint32_t& r3,
                                      uint32_t addr) {
    asm volatile("ldmatrix.sync.aligned.m8n8.x4.shared.b16 {%0,%1,%2,%3}, [%4];"
                 : "=r"(r0), "=r"(r1), "=r"(r2), "=r"(r3) : "r"(addr));
}
__device__ __forceinline__ void mma16816(float& d0, float& d1, float& d2, float& d3,
                                         uint32_t a0, uint32_t a1, uint32_t a2, uint32_t a3,
                                         uint32_t b0, uint32_t b1) {
    asm volatile("mma.sync.aligned.m16n8k16.row.col.f32.bf16.bf16.f32 "
                 "{%0,%1,%2,%3}, {%4,%5,%6,%7}, {%8,%9}, {%0,%1,%2,%3};"
                 : "+f"(d0), "+f"(d1), "+f"(d2), "+f"(d3)
                 : "r"(a0), "r"(a1), "r"(a2), "r"(a3), "r"(b0), "r"(b1));
}
__device__ __forceinline__ void mma16816h(float& d0, float& d1, float& d2, float& d3,
                                          uint32_t a0, uint32_t a1, uint32_t a2, uint32_t a3,
                                          uint32_t b0, uint32_t b1) {
    asm volatile("mma.sync.aligned.m16n8k16.row.col.f32.f16.f16.f32 "
                 "{%0,%1,%2,%3}, {%4,%5,%6,%7}, {%8,%9}, {%0,%1,%2,%3};"
                 : "+f"(d0), "+f"(d1), "+f"(d2), "+f"(d3)
                 : "r"(a0), "r"(a1), "r"(a2), "r"(a3), "r"(b0), "r"(b1));
}

__device__ __forceinline__ float gelu_exact(float x) {
    return 0.5f * x * (1.0f + erff(x * 0.70710678118654752f));
}

// swizzled 64B-row offset: row r, 16B chunk c (0..3)
__device__ __forceinline__ uint32_t swz(uint32_t r, uint32_t c) {
    return r * 64 + ((c ^ ((r >> 1) & 3)) << 4);
}

// pack 4 floats into bf16 hi/lo pairs (8B each)
__device__ __forceinline__ void split4(float o0, float o1, float o2, float o3,
                                       uint2& hv, uint2& lv) {
    __nv_bfloat162 h01 = __floats2bfloat162_rn(o0, o1);
    __nv_bfloat162 h23 = __floats2bfloat162_rn(o2, o3);
    float e0 = o0 - __bfloat162float(h01.x), e1 = o1 - __bfloat162float(h01.y);
    float e2 = o2 - __bfloat162float(h23.x), e3 = o3 - __bfloat162float(h23.y);
    __nv_bfloat162 l01 = __floats2bfloat162_rn(e0, e1);
    __nv_bfloat162 l23 = __floats2bfloat162_rn(e2, e3);
    hv = make_uint2(*(uint32_t*)&h01, *(uint32_t*)&h23);
    lv = make_uint2(*(uint32_t*)&l01, *(uint32_t*)&l23);
}

// ---------------- TM64 HMMA GEMM (bf16x3): CTA 64x128, BK=32, 4-stage ----------------
// 8 warps (2x4) of 32x32 tiles. MODE 0: fp32 + bias. MODE 1: gelu + bf16 hi/lo.
// ldc: output row stride (allows writing a column slice of a wider matrix).
#define S64_AHI 0
#define S64_ALO 4096
#define S64_BHI 8192
#define S64_BLO 16384
#define STAGE64 24576
#define GEMM64_SMEM (4*STAGE64)

template<int MODE>
__global__ __launch_bounds__(256, 2)
void gemm_hmma64(const __nv_bfloat16* __restrict__ Ahi, const __nv_bfloat16* __restrict__ Alo,
                 const __nv_bfloat16* __restrict__ Bhi, const __nv_bfloat16* __restrict__ Blo,
                 const float* __restrict__ bias, float* __restrict__ C,
                 __nv_bfloat16* __restrict__ Chi, __nv_bfloat16* __restrict__ Clo,
                 int N, int K, int ldc) {
    extern __shared__ char smem[];
    const uint32_t sb = smem_u32(smem);
    const int tid  = threadIdx.x;
    const int wid  = tid >> 5;
    const int lane = tid & 31;
    const int wrow = wid & 1;          // 32-row slab
    const int wcol = wid >> 1;         // 32-col slab
    const int bm = blockIdx.y << 6;
    const long bn = (long)blockIdx.x << 7;
    const int nc = K >> 5;

    const uint32_t rt = tid >> 2, ct = tid & 3;
    const uint32_t soA  = swz(rt, ct);
    const uint32_t soB1 = swz(rt + 64, ct);

    #define LOAD_STAGE64(kc, s) do {                                                   \
        uint32_t st_ = sb + (s) * STAGE64;                                              \
        size_t ga  = ((size_t)(bm + rt) * K + (kc) * 32 + ct * 8) * 2;                  \
        size_t gb0 = ((size_t)(bn + rt) * K + (kc) * 32 + ct * 8) * 2;                  \
        size_t gb1 = ((size_t)(bn + rt + 64) * K + (kc) * 32 + ct * 8) * 2;             \
        cp16(st_ + S64_AHI + soA,  (const char*)Ahi + ga);                              \
        cp16(st_ + S64_ALO + soA,  (const char*)Alo + ga);                              \
        cp16(st_ + S64_BHI + soA,  (const char*)Bhi + gb0);                             \
        cp16(st_ + S64_BLO + soA,  (const char*)Blo + gb0);                             \
        cp16(st_ + S64_BHI + soB1, (const char*)Bhi + gb1);                             \
        cp16(st_ + S64_BLO + soB1, (const char*)Blo + gb1);                             \
    } while (0)

    LOAD_STAGE64(0, 0); cp_commit();
    LOAD_STAGE64(1, 1); cp_commit();
    LOAD_STAGE64(2, 2); cp_commit();

    const int lane8 = lane & 7, sub = lane >> 3;
    const uint32_t ra = wrow * 32 + (sub & 1) * 8 + lane8;
    const uint32_t aks0 = swz(ra, (sub >> 1));
    const uint32_t aks1 = swz(ra, (sub >> 1) + 2);
    const uint32_t rb = wcol * 32 + lane8;
    const uint32_t boffs = swz(rb, sub);

    float acc[2][4][4];
    #pragma unroll
    for (int i = 0; i < 2; i++)
        #pragma unroll
        for (int j = 0; j < 4; j++)
            #pragma unroll
            for (int e = 0; e < 4; e++) acc[i][j][e] = 0.f;

    int slot = 0;
    for (int it = 0; it < nc; it++) {
        cp_wait<2>();
        __syncthreads();
        if (it + 3 < nc) {
            int ns = slot + 3; if (ns >= 4) ns -= 4;
            LOAD_STAGE64(it + 3, ns);
        }
        cp_commit();
        const uint32_t st = sb + slot * STAGE64;

        uint32_t bh[4][4], bl[4][4], ah[2][2][4], al[2][2][4];
        #pragma unroll
        for (int nj = 0; nj < 4; nj++) {
            ldsm4(bh[nj][0], bh[nj][1], bh[nj][2], bh[nj][3], st + S64_BHI + boffs + nj * 512);
            ldsm4(bl[nj][0], bl[nj][1], bl[nj][2], bl[nj][3], st + S64_BLO + boffs + nj * 512);
        }
        #pragma unroll
        for (int mi = 0; mi < 2; mi++) {
            ldsm4(ah[0][mi][0], ah[0][mi][1], ah[0][mi][2], ah[0][mi][3],
                  st + S64_AHI + aks0 + mi * 1024);
            ldsm4(ah[1][mi][0], ah[1][mi][1], ah[1][mi][2], ah[1][mi][3],
                  st + S64_AHI + aks1 + mi * 1024);
            ldsm4(al[0][mi][0], al[0][mi][1], al[0][mi][2], al[0][mi][3],
                  st + S64_ALO + aks0 + mi * 1024);
            ldsm4(al[1][mi][0], al[1][mi][1], al[1][mi][2], al[1][mi][3],
                  st + S64_ALO + aks1 + mi * 1024);
        }
        #pragma unroll
        for (int ks = 0; ks < 2; ks++) {
            #pragma unroll
            for (int mi = 0; mi < 2; mi++)
                #pragma unroll
                for (int nj = 0; nj < 4; nj++)
                    mma16816(acc[mi][nj][0], acc[mi][nj][1], acc[mi][nj][2], acc[mi][nj][3],
                             ah[ks][mi][0], ah[ks][mi][1], ah[ks][mi][2], ah[ks][mi][3],
                             bh[nj][ks * 2], bh[nj][ks * 2 + 1]);
            #pragma unroll
            for (int mi = 0; mi < 2; mi++)
                #pragma unroll
                for (int nj = 0; nj < 4; nj++)
                    mma16816(acc[mi][nj][0], acc[mi][nj][1], acc[mi][nj][2], acc[mi][nj][3],
                             ah[ks][mi][0], ah[ks][mi][1], ah[ks][mi][2], ah[ks][mi][3],
                             bl[nj][ks * 2], bl[nj][ks * 2 + 1]);
            #pragma unroll
            for (int mi = 0; mi < 2; mi++)
                #pragma unroll
                for (int nj = 0; nj < 4; nj++)
                    mma16816(acc[mi][nj][0], acc[mi][nj][1], acc[mi][nj][2], acc[mi][nj][3],
                             al[ks][mi][0], al[ks][mi][1], al[ks][mi][2], al[ks][mi][3],
                             bh[nj][ks * 2], bh[nj][ks * 2 + 1]);
        }
        if (++slot == 4) slot = 0;
    }

    const int gr = lane >> 2;
    const int gc = (lane & 3) * 2;
    #pragma unroll
    for (int mi = 0; mi < 2; mi++) {
        size_t row0 = (size_t)(bm + wrow * 32 + mi * 16 + gr) * ldc;
        size_t row1 = row0 + (size_t)8 * ldc;
        #pragma unroll
        for (int nj = 0; nj < 4; nj++) {
            long c = bn + wcol * 32 + nj * 8 + gc;
            float b0 = bias[c], b1 = bias[c + 1];
            if (MODE == 0) {
                C[row0 + c]     = acc[mi][nj][0] + b0;
                C[row0 + c + 1] = acc[mi][nj][1] + b1;
                C[row1 + c]     = acc[mi][nj][2] + b0;
                C[row1 + c + 1] = acc[mi][nj][3] + b1;
            } else {
                float v0 = gelu_exact(acc[mi][nj][0] + b0);
                float v1 = gelu_exact(acc[mi][nj][1] + b1);
                float v2 = gelu_exact(acc[mi][nj][2] + b0);
                float v3 = gelu_exact(acc[mi][nj][3] + b1);
                __nv_bfloat162 hp0 = __floats2bfloat162_rn(v0, v1);
                __nv_bfloat162 hp1 = __floats2bfloat162_rn(v2, v3);
                float e0 = v0 - __bfloat162float(hp0.x), e1 = v1 - __bfloat162float(hp0.y);
                float e2 = v2 - __bfloat162float(hp1.x), e3 = v3 - __bfloat162float(hp1.y);
                __nv_bfloat162 lp0 = __floats2bfloat162_rn(e0, e1);
                __nv_bfloat162 lp1 = __floats2bfloat162_rn(e2, e3);
                *(uint32_t*)(Chi + row0 + c) = *(uint32_t*)&hp0;
                *(uint32_t*)(Clo + row0 + c) = *(uint32_t*)&lp0;
                *(uint32_t*)(Chi + row1 + c) = *(uint32_t*)&hp1;
                *(uint32_t*)(Clo + row1 + c) = *(uint32_t*)&lp1;
            }
        }
    }
    #undef LOAD_STAGE64
}

// ---------------- single-pass bf16 GEMM for Q/K (precision-insensitive) ----------------
// CTA 64x128, BK=32, 4-stage. Only hi operands. fp32 out (no bias), strided ldc.
#define QK_A 0
#define QK_B 4096
#define STAGE_QK 12288
#define QK_SMEM (4*STAGE_QK)

__global__ __launch_bounds__(256, 2)
void gemm_qk(const __nv_bfloat16* __restrict__ Ahi, const __nv_bfloat16* __restrict__ Bhi,
             float* __restrict__ C, int K, int ldc) {
    extern __shared__ char smem[];
    const uint32_t sb = smem_u32(smem);
    const int tid  = threadIdx.x;
    const int wid  = tid >> 5;
    const int lane = tid & 31;
    const int wrow = wid & 1;
    const int wcol = wid >> 1;
    const int bm = blockIdx.y << 6;
    const long bn = (long)blockIdx.x << 7;
    const int nc = K >> 5;

    const uint32_t rt = tid >> 2, ct = tid & 3;
    const uint32_t soA  = swz(rt, ct);
    const uint32_t soB1 = swz(rt + 64, ct);

    #define LOAD_STAGE_QK(kc, s) do {                                                  \
        uint32_t st_ = sb + (s) * STAGE_QK;                                             \
        size_t ga  = ((size_t)(bm + rt) * K + (kc) * 32 + ct * 8) * 2;                  \
        size_t gb0 = ((size_t)(bn + rt) * K + (kc) * 32 + ct * 8) * 2;                  \
        size_t gb1 = ((size_t)(bn + rt + 64) * K + (kc) * 32 + ct * 8) * 2;             \
        cp16(st_ + QK_A + soA,  (const char*)Ahi + ga);                                 \
        cp16(st_ + QK_B + soA,  (const char*)Bhi + gb0);                                \
        cp16(st_ + QK_B + soB1, (const char*)Bhi + gb1);                                \
    } while (0)

    LOAD_STAGE_QK(0, 0); cp_commit();
    LOAD_STAGE_QK(1, 1); cp_commit();
    LOAD_STAGE_QK(2, 2); cp_commit();

    const int lane8 = lane & 7, sub = lane >> 3;
    const uint32_t ra = wrow * 32 + (sub & 1) * 8 + lane8;
    const uint32_t aks0 = swz(ra, (sub >> 1));
    const uint32_t aks1 = swz(ra, (sub >> 1) + 2);
    const uint32_t rb = wcol * 32 + lane8;
    const uint32_t boffs = swz(rb, sub);

    float acc[2][4][4];
    #pragma unroll
    for (int i = 0; i < 2; i++)
        #pragma unroll
        for (int j = 0; j < 4; j++)
            #pragma unroll
            for (int e = 0; e < 4; e++) acc[i][j][e] = 0.f;

    int slot = 0;
    for (int it = 0; it < nc; it++) {
        cp_wait<2>();
        __syncthreads();
        if (it + 3 < nc) {
            int ns = slot + 3; if (ns >= 4) ns -= 4;
            LOAD_STAGE_QK(it + 3, ns);
        }
        cp_commit();
        const uint32_t st = sb + slot * STAGE_QK;

        uint32_t bh[4][4], ah[2][2][4];
        #pragma unroll
        for (int nj = 0; nj < 4; nj++)
            ldsm4(bh[nj][0], bh[nj][1], bh[nj][2], bh[nj][3], st + QK_B + boffs + nj * 512);
        #pragma unroll
        for (int mi = 0; mi < 2; mi++) {
            ldsm4(ah[0][mi][0], ah[0][mi][1], ah[0][mi][2], ah[0][mi][3],
                  st + QK_A + aks0 + mi * 1024);
            ldsm4(ah[1][mi][0], ah[1][mi][1], ah[1][mi][2], ah[1][mi][3],
                  st + QK_A + aks1 + mi * 1024);
        }
        #pragma unroll
        for (int ks = 0; ks < 2; ks++)
            #pragma unroll
            for (int mi = 0; mi < 2; mi++)
                #pragma unroll
                for (int nj = 0; nj < 4; nj++)
                    mma16816(acc[mi][nj][0], acc[mi][nj][1], acc[mi][nj][2], acc[mi][nj][3],
                             ah[ks][mi][0], ah[ks][mi][1], ah[ks][mi][2], ah[ks][mi][3],
                             bh[nj][ks * 2], bh[nj][ks * 2 + 1]);
        if (++slot == 4) slot = 0;
    }

    const int gr = lane >> 2;
    const int gc = (lane & 3) * 2;
    #pragma unroll
    for (int mi = 0; mi < 2; mi++) {
        size_t row0 = (size_t)(bm + wrow * 32 + mi * 16 + gr) * ldc;
        size_t row1 = row0 + (size_t)8 * ldc;
        #pragma unroll
        for (int nj = 0; nj < 4; nj++) {
            long c = bn + wcol * 32 + nj * 8 + gc;
            C[row0 + c]     = acc[mi][nj][0];
            C[row0 + c + 1] = acc[mi][nj][1];
            C[row1 + c]     = acc[mi][nj][2];
            C[row1 + c + 1] = acc[mi][nj][3];
        }
    }
    #undef LOAD_STAGE_QK
}

// ---------------- fp16 single-term GEMM (LM head), 4-stage ----------------
#define F_TA 0
#define F_TB 8192
#define F_STAGE 16384
#define F16_SMEM (4*F_STAGE)

__global__ __launch_bounds__(256, 2)
void gemm_f16(const __half* __restrict__ A, const __half* __restrict__ B,
              const float* __restrict__ bias, float* __restrict__ C, int N, int K) {
    extern __shared__ char smem[];
    const uint32_t sb = smem_u32(smem);
    const int tid  = threadIdx.x;
    const int wid  = tid >> 5;
    const int lane = tid & 31;
    const int wrow = wid & 1;
    const int wcol = wid >> 1;
    const int bm = blockIdx.x << 7;
    const long bn = (long)blockIdx.y << 7;
    const int nc = K >> 5;

    const uint32_t r0t = tid >> 2, c0t = tid & 3;
    const uint32_t r1t = r0t + 64;
    const uint32_t so0 = swz(r0t, c0t);
    const uint32_t so1 = swz(r1t, c0t);

    #define LOAD_STAGE_F(kc, s) do {                                                   \
        uint32_t st_ = sb + (s) * F_STAGE;                                              \
        {                                                                               \
            size_t ga = ((size_t)(bm + r0t) * K + (kc) * 32 + c0t * 8) * 2;             \
            size_t gb = ((size_t)(bn + r0t) * K + (kc) * 32 + c0t * 8) * 2;             \
            cp16(st_ + F_TA + so0, (const char*)A + ga);                                \
            cp16(st_ + F_TB + so0, (const char*)B + gb);                                \
        }                                                                               \
        {                                                                               \
            size_t ga = ((size_t)(bm + r1t) * K + (kc) * 32 + c0t * 8) * 2;             \
            size_t gb = ((size_t)(bn + r1t) * K + (kc) * 32 + c0t * 8) * 2;             \
            cp16(st_ + F_TA + so1, (const char*)A + ga);                                \
            cp16(st_ + F_TB + so1, (const char*)B + gb);                                \
        }                                                                               \
    } while (0)

    LOAD_STAGE_F(0, 0); cp_commit();
    LOAD_STAGE_F(1, 1); cp_commit();
    LOAD_STAGE_F(2, 2); cp_commit();

    const int lane8 = lane & 7, sub = lane >> 3;
    const uint32_t ra = wrow * 64 + (sub & 1) * 8 + lane8;
    const uint32_t aks0 = swz(ra, (sub >> 1));
    const uint32_t aks1 = swz(ra, (sub >> 1) + 2);
    const uint32_t rb = wcol * 32 + lane8;
    const uint32_t boffs = swz(rb, sub);

    float acc[4][4][4];
    #pragma unroll
    for (int i = 0; i < 4; i++)
        #pragma unroll
        for (int j = 0; j < 4; j++)
            #pragma unroll
            for (int e = 0; e < 4; e++) acc[i][j][e] = 0.f;

    int slot = 0;
    for (int it = 0; it < nc; it++) {
        cp_wait<2>();
        __syncthreads();
        if (it + 3 < nc) {
            int ns = slot + 3; if (ns >= 4) ns -= 4;
            LOAD_STAGE_F(it + 3, ns);
        }
        cp_commit();
        const uint32_t st = sb + slot * F_STAGE;

        uint32_t bf[4][4];
        #pragma unroll
        for (int nj = 0; nj < 4; nj++)
            ldsm4(bf[nj][0], bf[nj][1], bf[nj][2], bf[nj][3], st + F_TB + boffs + nj * 512);
        #pragma unroll
        for (int ks = 0; ks < 2; ks++) {
            const uint32_t ao = (ks == 0) ? aks0 : aks1;
            uint32_t a[4][4];
            #pragma unroll
            for (int mi = 0; mi < 4; mi++)
                ldsm4(a[mi][0], a[mi][1], a[mi][2], a[mi][3], st + F_TA + ao + mi * 1024);
            #pragma unroll
            for (int mi = 0; mi < 4; mi++)
                #pragma unroll
                for (int nj = 0; nj < 4; nj++)
                    mma16816h(acc[mi][nj][0], acc[mi][nj][1], acc[mi][nj][2], acc[mi][nj][3],
                              a[mi][0], a[mi][1], a[mi][2], a[mi][3],
                              bf[nj][ks * 2], bf[nj][ks * 2 + 1]);
        }
        if (++slot == 4) slot = 0;
    }

    const int gr = lane >> 2;
    const int gc = (lane & 3) * 2;
    #pragma unroll
    for (int mi = 0; mi < 4; mi++) {
        size_t row0 = (size_t)(bm + wrow * 64 + mi * 16 + gr) * N;
        size_t row1 = row0 + (size_t)8 * N;
        #pragma unroll
        for (int nj = 0; nj < 4; nj++) {
            long c = bn + wcol * 32 + nj * 8 + gc;
            if (c < N) {
                C[row0 + c] = acc[mi][nj][0] + bias[c];
                C[row1 + c] = acc[mi][nj][2] + bias[c];
            }
            if (c + 1 < N) {
                C[row0 + c + 1] = acc[mi][nj][1] + bias[c + 1];
                C[row1 + c + 1] = acc[mi][nj][3] + bias[c + 1];
            }
        }
    }
    #undef LOAD_STAGE_F
}

// ---------------- weight transpose + split (bf16 hi/lo) ----------------
template<int QKV>
__global__ __launch_bounds__(256)
void transpose_split(const float* __restrict__ src0, const float* __restrict__ src1,
                     const float* __restrict__ src2,
                     __nv_bfloat16* __restrict__ hi, __nv_bfloat16* __restrict__ lo,
                     int R, int C) {
    __shared__ float t[128][33];
    int z = blockIdx.z;
    const float* src = src0;
    int sel = 0;
    if (QKV) {
        sel = z / (NLAYERS * NH);
        z   = z % (NLAYERS * NH);
        src = (sel == 0) ? src0 : (sel == 1) ? src1 : src2;
    }
    const size_t ib = (size_t)z * R * C;
    size_t ob;
    if (QKV) ob = (size_t)(z >> 4) * (3072 * 1024) + (size_t)sel * (1024 * 1024)
                + (size_t)(z & 15) * (64 * 1024);
    else     ob = ib;
    const int r0 = blockIdx.y * 128, c0 = blockIdx.x * 32;
    const int cc = threadIdx.x & 31, rb = threadIdx.x >> 5;
    const bool cok = (c0 + cc) < C;
    #pragma unroll
    for (int p = 0; p < 16; p++) {
        int rr = rb + p * 8;
        t[rr][cc] = cok ? src[ib + (size_t)(r0 + rr) * C + c0 + cc] : 0.f;
    }
    __syncthreads();
    const int oc = threadIdx.x >> 3, rq8 = threadIdx.x & 7;
    if (c0 + oc < C) {
        size_t obase = ob + (size_t)(c0 + oc) * R + r0;
        #pragma unroll
        for (int p = 0; p < 4; p++) {
            int r = (rq8 + p * 8) * 4;
            uint2 hv, lv;
            split4(t[r][oc], t[r + 1][oc], t[r + 2][oc], t[r + 3][oc], hv, lv);
            *(uint2*)(hi + obase + r) = hv;
            *(uint2*)(lo + obase + r) = lv;
        }
    }
}

// ---------------- fp16 weight transpose (LM head) ----------------
__global__ __launch_bounds__(256)
void transpose_f16(const float* __restrict__ src, __half* __restrict__ out, int R, int C) {
    __shared__ float t[128][33];
    const int r0 = blockIdx.y * 128, c0 = blockIdx.x * 32;
    const int cc = threadIdx.x & 31, rb = threadIdx.x >> 5;
    const bool cok = (c0 + cc) < C;
    #pragma unroll
    for (int p = 0; p < 16; p++) {
        int rr = rb + p * 8;
        t[rr][cc] = cok ? src[(size_t)(r0 + rr) * C + c0 + cc] : 0.f;
    }
    __syncthreads();
    const int oc = threadIdx.x >> 3, rq8 = threadIdx.x & 7;
    if (c0 + oc < C) {
        size_t obase = (size_t)(c0 + oc) * R + r0;
        #pragma unroll
        for (int p = 0; p < 4; p++) {
            int r = (rq8 + p * 8) * 4;
            __half2 h0 = __floats2half2_rn(t[r][oc], t[r + 1][oc]);
            __half2 h1 = __floats2half2_rn(t[r + 2][oc], t[r + 3][oc]);
            *(uint2*)(out + obase + r) = make_uint2(*(uint32_t*)&h0, *(uint32_t*)&h1);
        }
    }
}

// ---------------- embedding: x = emb[tok] + pos, + split ----------------
__global__ void embed_kernel(const int* __restrict__ tok, const float* __restrict__ emb,
                             const float* __restrict__ pos, float* __restrict__ x,
                             __nv_bfloat16* __restrict__ hi, __nv_bfloat16* __restrict__ lo) {
    int i4 = blockIdx.x * 256 + threadIdx.x;
    int e = i4 * 4;
    int s = e >> 10, h = e & 1023;
    float4 ev = *(const float4*)(emb + (size_t)tok[s] * H + h);
    float4 pv = *(const float4*)(pos + e);
    float o0 = ev.x + pv.x, o1 = ev.y + pv.y, o2 = ev.z + pv.z, o3 = ev.w + pv.w;
    *(float4*)(x + e) = make_float4(o0, o1, o2, o3);
    uint2 hv, lv;
    split4(o0, o1, o2, o3, hv, lv);
    *(uint2*)(hi + e) = hv;
    *(uint2*)(lo + e) = lv;
}

// ---------------- M_part = K^T V per (head, seg); 8 segs ----------------
__global__ __launch_bounds__(256)
void ktv_kernel(const float* __restrict__ qkv, float* __restrict__ mp) {
    const int head = blockIdx.x & 15, seg = blockIdx.x >> 4;   // seg 0..7
    __shared__ float Ks[64][65];
    __shared__ float Vs[64][65];
    const int tid = threadIdx.x;
    const int tr = tid >> 4, tc = tid & 15;
    float acc[4][4] = {};
    for (int t0 = seg * 256; t0 < seg * 256 + 256; t0 += 64) {
        for (int i = tid; i < 4096; i += 256) {
            int r = i >> 6, c = i & 63;
            size_t base = (size_t)(t0 + r) * 3072 + head * DH + c;
            Ks[r][c] = qkv[base + 1024];
            Vs[r][c] = qkv[base + 2048];
        }
        __syncthreads();
        #pragma unroll 4
        for (int t = 0; t < 64; t++) {
            float a[4], b[4];
            #pragma unroll
            for (int i = 0; i < 4; i++) a[i] = Ks[t][tr * 4 + i];
            #pragma unroll
            for (int j = 0; j < 4; j++) b[j] = Vs[t][tc * 4 + j];
            #pragma unroll
            for (int i = 0; i < 4; i++)
                #pragma unroll
                for (int j = 0; j < 4; j++)
                    acc[i][j] = fmaf(a[i], b[j], acc[i][j]);
        }
        __syncthreads();
    }
    #pragma unroll
    for (int i = 0; i < 4; i++)
        #pragma unroll
        for (int j = 0; j < 4; j++)
            mp[(size_t)(seg * 16 + head) * 4096 + (tr * 4 + i) * 64 + tc * 4 + j] = acc[i][j];
}

// ---------------- parallel suffix sum of V over S ----------------
__global__ void suf_partial(const float* __restrict__ qkv, float* __restrict__ part) {
    int col = blockIdx.y * 256 + threadIdx.x;
    int seg = blockIdx.x;
    float s = 0.f;
    for (int t = seg * 128; t < seg * 128 + 128; t++)
        s += qkv[(size_t)t * 3072 + 2048 + col];
    part[seg * 1024 + col] = s;
}
__global__ void suf_apply(const float* __restrict__ qkv, const float* __restrict__ part,
                          float* __restrict__ suf) {
    int col = blockIdx.y * 256 + threadIdx.x;
    int seg = blockIdx.x;
    float run = 0.f;
    for (int s2 = seg + 1; s2 < 16; s2++) run += part[s2 * 1024 + col];
    for (int t = seg * 128 + 127; t >= seg * 128; t--) {
        suf[(size_t)t * 1024 + col] = run;
        run += qkv[(size_t)t * 3072 + 2048 + col];
    }
}

// ---------------- attn = scale*(Q@M) - 1e9*suf, emit hi/lo split ----------------
__global__ __launch_bounds__(256)
void attn_combine(const float* __restrict__ qkv, const float* __restrict__ mp,
                  const float* __restrict__ suf,
                  __nv_bfloat16* __restrict__ ahi, __nv_bfloat16* __restrict__ alo) {
    const int head = blockIdx.y;
    const int s0 = blockIdx.x * 64;
    __shared__ float Qs[64][65];
    __shared__ float Ms[64][65];
    const int tid = threadIdx.x;
    for (int i = tid; i < 4096; i += 256) {
        int r = i >> 6, c = i & 63;
        Qs[r][c] = qkv[(size_t)(s0 + r) * 3072 + head * DH + c];
        float mv = 0.f;
        #pragma unroll
        for (int sg = 0; sg < 8; sg++) mv += mp[(size_t)(sg * 16 + head) * 4096 + i];
        Ms[r][c] = mv;
    }
    __syncthreads();
    const int tr = tid >> 4, tc = tid & 15;
    float acc[4][4] = {};
    #pragma unroll 4
    for (int hp = 0; hp < 64; hp++) {
        float a[4], b[4];
        #pragma unroll
        for (int i = 0; i < 4; i++) a[i] = Qs[tr * 4 + i][hp];
        #pragma unroll
        for (int j = 0; j < 4; j++) b[j] = Ms[hp][tc * 4 + j];
        #pragma unroll
        for (int i = 0; i < 4; i++)
            #pragma unroll
            for (int j = 0; j < 4; j++)
                acc[i][j] = fmaf(a[i], b[j], acc[i][j]);
    }
    #pragma unroll
    for (int i = 0; i < 4; i++) {
        int s = s0 + tr * 4 + i;
        size_t sb = (size_t)s * 1024 + head * DH + tc * 4;
        float o[4];
        #pragma unroll
        for (int j = 0; j < 4; j++)
            o[j] = 0.125f * acc[i][j] - 1e9f * suf[sb + j];
        uint2 hv, lv;
        split4(o[0], o[1], o[2], o[3], hv, lv);
        *(uint2*)(ahi + sb) = hv;
        *(uint2*)(alo + sb) = lv;
    }
}

// ---------------- LayerNorm (+residual) + fused split ----------------
template<bool ADD, bool WF32, int OUTK>
__global__ __launch_bounds__(256)
void ln_kernel(const float* __restrict__ t, const float* __restrict__ xin,
               const float* __restrict__ g, const float* __restrict__ b,
               float* __restrict__ outf,
               __nv_bfloat16* __restrict__ hi, __nv_bfloat16* __restrict__ lo,
               __half* __restrict__ outh) {
    const int row = blockIdx.x;
    const int tid = threadIdx.x;
    float4 v = *(const float4*)(t + (size_t)row * H + tid * 4);
    __shared__ float red[256];
    __shared__ float stat[2];

    float s = v.x + v.y + v.z + v.w;
    red[tid] = s; __syncthreads();
    for (int o = 128; o > 0; o >>= 1) {
        if (tid < o) red[tid] += red[tid + o];
        __syncthreads();
    }
    if (tid == 0) stat[0] = red[0] * (1.0f / H);
    __syncthreads();
    float mean = stat[0];

    float dx = v.x - mean, dy = v.y - mean, dz = v.z - mean, dw = v.w - mean;
    red[tid] = dx * dx + dy * dy + dz * dz + dw * dw; __syncthreads();
    for (int o = 128; o > 0; o >>= 1) {
        if (tid < o) red[tid] += red[tid + o];
        __syncthreads();
    }
    if (tid == 0) stat[1] = rsqrtf(red[0] * (1.0f / H) + 1e-5f);
    __syncthreads();
    float rstd = stat[1];

    int h = tid * 4;
    float4 gv = *(const float4*)(g + h);
    float4 bv = *(const float4*)(b + h);
    float o0 = dx * rstd * gv.x + bv.x;
    float o1 = dy * rstd * gv.y + bv.y;
    float o2 = dz * rstd * gv.z + bv.z;
    float o3 = dw * rstd * gv.w + bv.w;
    if (ADD) {
        float4 xv = *(const float4*)(xin + (size_t)row * H + h);
        o0 += xv.x; o1 += xv.y; o2 += xv.z; o3 += xv.w;
    }
    if (WF32) *(float4*)(outf + (size_t)row * H + h) = make_float4(o0, o1, o2, o3);
    if (OUTK == 0) {
        uint2 hv, lv;
        split4(o0, o1, o2, o3, hv, lv);
        *(uint2*)(hi + (size_t)row * H + h) = hv;
        *(uint2*)(lo + (size_t)row * H + h) = lv;
    } else {
        __half2 h0 = __floats2half2_rn(o0, o1);
        __half2 h1 = __floats2half2_rn(o2, o3);
        *(uint2*)(outh + (size_t)row * H + h) = make_uint2(*(uint32_t*)&h0, *(uint32_t*)&h1);
    }
}

// ---------------- launch ----------------
extern "C" void kernel_launch(void* const* d_in, const int* in_sizes, int n_in,
                              void* d_out, int out_size) {
    const int*   tokens = (const int*)  d_in[0];
    const float* emb    = (const float*)d_in[1];
    const float* pos    = (const float*)d_in[2];
    const float* Wq     = (const float*)d_in[3];
    const float* Wk     = (const float*)d_in[4];
    const float* Wv     = (const float*)d_in[5];
    const float* Wp     = (const float*)d_in[6];
    const float* bp     = (const float*)d_in[7];
    const float* W1     = (const float*)d_in[8];
    const float* b1     = (const float*)d_in[9];
    const float* W2     = (const float*)d_in[10];
    const float* b2     = (const float*)d_in[11];
    const float* ln_g   = (const float*)d_in[12];
    const float* ln_b   = (const float*)d_in[13];
    const float* Wlm    = (const float*)d_in[14];
    const float* blm    = (const float*)d_in[15];
    float* out = (float*)d_out;
    const int Vv = in_sizes[15];

    float *x, *tmp, *res, *qkv, *suf, *m, *part, *zb;
    __nv_bfloat16 *ahi, *alo, *bhi, *blo;
    __nv_bfloat16 *btqkv_hi, *btqkv_lo, *btp_hi, *btp_lo;
    __nv_bfloat16 *bt1_hi, *bt1_lo, *bt2_hi, *bt2_lo;
    __half *wlm, *xf16;
    cudaGetSymbolAddress((void**)&x, g_x);       cudaGetSymbolAddress((void**)&tmp, g_tmp);
    cudaGetSymbolAddress((void**)&res, g_res);   cudaGetSymbolAddress((void**)&qkv, g_qkv);
    cudaGetSymbolAddress((void**)&suf, g_suf);   cudaGetSymbolAddress((void**)&m, g_m);
    cudaGetSymbolAddress((void**)&part, g_part); cudaGetSymbolAddress((void**)&zb, g_zb);
    cudaGetSymbolAddress((void**)&ahi, g_ahi);   cudaGetSymbolAddress((void**)&alo, g_alo);
    cudaGetSymbolAddress((void**)&bhi, g_bhi);   cudaGetSymbolAddress((void**)&blo, g_blo);
    cudaGetSymbolAddress((void**)&btqkv_hi, g_btqkv_hi);
    cudaGetSymbolAddress((void**)&btqkv_lo, g_btqkv_lo);
    cudaGetSymbolAddress((void**)&btp_hi, g_btp_hi); cudaGetSymbolAddress((void**)&btp_lo, g_btp_lo);
    cudaGetSymbolAddress((void**)&bt1_hi, g_bt1_hi); cudaGetSymbolAddress((void**)&bt1_lo, g_bt1_lo);
    cudaGetSymbolAddress((void**)&bt2_hi, g_bt2_hi); cudaGetSymbolAddress((void**)&bt2_lo, g_bt2_lo);
    cudaGetSymbolAddress((void**)&wlm, g_wlm_f16);   cudaGetSymbolAddress((void**)&xf16, g_xf_f16);

    cudaFuncSetAttribute(gemm_hmma64<0>, cudaFuncAttributeMaxDynamicSharedMemorySize, GEMM64_SMEM);
    cudaFuncSetAttribute(gemm_hmma64<1>, cudaFuncAttributeMaxDynamicSharedMemorySize, GEMM64_SMEM);
    cudaFuncSetAttribute(gemm_qk, cudaFuncAttributeMaxDynamicSharedMemorySize, QK_SMEM);
    cudaFuncSetAttribute(gemm_f16, cudaFuncAttributeMaxDynamicSharedMemorySize, F16_SMEM);

    dim3 tb(256);
    // idx0: embed
    embed_kernel<<<(S * H) / 1024, 256>>>(tokens, emb, pos, x, ahi, alo);
    // idx1: combined qkv weight transpose
    transpose_split<1><<<dim3(2, 8, 3 * NLAYERS * NH), tb>>>(Wq, Wk, Wv,
                                                             btqkv_hi, btqkv_lo, H, DH);
    // idx2: proj weights
    transpose_split<0><<<dim3(32, 8, NLAYERS), tb>>>(Wp, nullptr, nullptr,
                                                     btp_hi, btp_lo, H, H);
    // idx3: V GEMM layer 0 (bf16x3, N=1024) -> qkv cols 2048..3071
    gemm_hmma64<0><<<dim3(8, 32), 256, GEMM64_SMEM>>>(ahi, alo,
        btqkv_hi + (size_t)2048 * 1024, btqkv_lo + (size_t)2048 * 1024,
        zb, qkv + 2048, nullptr, nullptr, 1024, H, 3072);
    // idx4: QK GEMM layer 0 (bf16 single-pass, N=2048) -> qkv cols 0..2047
    gemm_qk<<<dim3(16, 32), 256, QK_SMEM>>>(ahi, btqkv_hi, qkv, H, 3072);
    // remaining weight transposes
    transpose_split<0><<<dim3(128, 8, NLAYERS), tb>>>(W1, nullptr, nullptr, bt1_hi, bt1_lo, H, FF);
    transpose_split<0><<<dim3(32, 32, NLAYERS), tb>>>(W2, nullptr, nullptr, bt2_hi, bt2_lo, FF, H);
    transpose_f16<<<dim3((Vv + 31) / 32, 8), tb>>>(Wlm, wlm, H, Vv);

    for (int l = 0; l < NLAYERS; l++) {
        size_t oQ = (size_t)l * 3072 * H;
        size_t oH = (size_t)l * H * H;
        size_t oF = (size_t)l * H * FF;

        if (l > 0) {
            gemm_hmma64<0><<<dim3(8, 32), 256, GEMM64_SMEM>>>(ahi, alo,
                btqkv_hi + oQ + (size_t)2048 * 1024, btqkv_lo + oQ + (size_t)2048 * 1024,
                zb, qkv + 2048, nullptr, nullptr, 1024, H, 3072);
            gemm_qk<<<dim3(16, 32), 256, QK_SMEM>>>(ahi, btqkv_hi + oQ, qkv, H, 3072);
        }
        ktv_kernel<<<128, 256>>>(qkv, m);
        suf_partial<<<dim3(16, 4), 256>>>(qkv, part);
        suf_apply<<<dim3(16, 4), 256>>>(qkv, part, suf);
        attn_combine<<<dim3(S / 64, NH), 256>>>(qkv, m, suf, ahi, alo);

        gemm_hmma64<0><<<dim3(8, 32), 256, GEMM64_SMEM>>>(ahi, alo, btp_hi + oH, btp_lo + oH,
                                                          bp + (size_t)l * H, tmp, nullptr, nullptr,
                                                          H, H, H);
        ln_kernel<true, true, 0><<<S, 256>>>(tmp, x, ln_g, ln_b, res, ahi, alo, nullptr);

        gemm_hmma64<1><<<dim3(32, 32), 256, GEMM64_SMEM>>>(ahi, alo, bt1_hi + oF, bt1_lo + oF,
                                                           b1 + (size_t)l * FF, nullptr, bhi, blo,
                                                           FF, H, FF);
        gemm_hmma64<0><<<dim3(8, 32), 256, GEMM64_SMEM>>>(bhi, blo, bt2_hi + oF, bt2_lo + oF,
                                                          b2 + (size_t)l * H, tmp, nullptr, nullptr,
                                                          H, FF, H);
        ln_kernel<true, true, 0><<<S, 256>>>(tmp, res, ln_g, ln_b, x, ahi, alo, nullptr);
    }

    // final LN -> fp16, LM head in fp16 HMMA
    ln_kernel<false, false, 1><<<S, 256>>>(x, nullptr, ln_g, ln_b, nullptr, nullptr, nullptr, xf16);
    gemm_f16<<<dim3(16, VPAD / 128), 256, F16_SMEM>>>(xf16, wlm, blm, out, Vv, H);
}

// round 10
// speedup vs baseline: 1.4932x; 1.4932x over previous
#include <cuda_runtime.h>
#include <cuda_bf16.h>
#include <cuda_fp16.h>
#include <math.h>
#include <stdint.h>

#define S  2048
#define H  1024
#define NH 16
#define DH 64
#define FF 4096
#define NLAYERS 6
#define VPAD 50432     // 50257 padded to multiple of 128

#define SZ_SH (S*H)

// ---------------- device scratch ----------------
__device__ __align__(16) float g_x[SZ_SH];
__device__ __align__(16) float g_tmp[SZ_SH];
__device__ __align__(16) float g_res[SZ_SH];
__device__ __align__(16) float g_qkv[S*3072];
__device__ __align__(16) float g_suf[SZ_SH];
__device__ __align__(16) float g_m[8*NH*DH*DH];     // split-K partials
__device__ __align__(16) float g_part[16*1024];
__device__ __align__(16) float g_zb[8192];          // zero bias (never written)

// activation hi/lo
__device__ __align__(128) __nv_bfloat16 g_ahi[S*FF];
__device__ __align__(128) __nv_bfloat16 g_alo[S*FF];
__device__ __align__(128) __nv_bfloat16 g_bhi[S*FF];
__device__ __align__(128) __nv_bfloat16 g_blo[S*FF];

// weight hi/lo, K-major transposed [N,K]
__device__ __align__(128) __nv_bfloat16 g_btqkv_hi[NLAYERS*3072*H];
__device__ __align__(128) __nv_bfloat16 g_btqkv_lo[NLAYERS*3072*H];
__device__ __align__(128) __nv_bfloat16 g_btp_hi[NLAYERS*H*H];
__device__ __align__(128) __nv_bfloat16 g_btp_lo[NLAYERS*H*H];
__device__ __align__(128) __nv_bfloat16 g_bt1_hi[NLAYERS*H*FF];
__device__ __align__(128) __nv_bfloat16 g_bt1_lo[NLAYERS*H*FF];
__device__ __align__(128) __nv_bfloat16 g_bt2_hi[NLAYERS*H*FF];
__device__ __align__(128) __nv_bfloat16 g_bt2_lo[NLAYERS*H*FF];
__device__ __align__(128) __half g_wlm_f16[VPAD*H];  // fp16 LM weights, pad rows stay zero
__device__ __align__(128) __half g_xf_f16[SZ_SH];    // fp16 final-LN activations

// ---------------- PTX helpers ----------------
__device__ __forceinline__ uint32_t smem_u32(const void* p) {
    uint32_t a;
    asm("{ .reg .u64 t; cvta.to.shared.u64 t, %1; cvt.u32.u64 %0, t; }" : "=r"(a) : "l"(p));
    return a;
}
__device__ __forceinline__ void cp16(uint32_t dst, const void* src) {
    asm volatile("cp.async.cg.shared.global [%0], [%1], 16;" :: "r"(dst), "l"(src));
}
__device__ __forceinline__ void cp_commit() { asm volatile("cp.async.commit_group;" ::: "memory"); }
template<int N> __device__ __forceinline__ void cp_wait() {
    asm volatile("cp.async.wait_group %0;" :: "n"(N) : "memory");
}
__device__ __forceinline__ void ldsm4(uint32_t& r0, uint32_t& r1, uint32_t& r2, uint32_t& r3,
                                      uint32_t addr) {
    asm volatile("ldmatrix.sync.aligned.m8n8.x4.shared.b16 {%0,%1,%2,%3}, [%4];"
                 : "=r"(r0), "=r"(r1), "=r"(r2), "=r"(r3) : "r"(addr));
}
__device__ __forceinline__ void mma16816(float& d0, float& d1, float& d2, float& d3,
                                         uint32_t a0, uint32_t a1, uint32_t a2, uint32_t a3,
                                         uint32_t b0, uint32_t b1) {
    asm volatile("mma.sync.aligned.m16n8k16.row.col.f32.bf16.bf16.f32 "
                 "{%0,%1,%2,%3}, {%4,%5,%6,%7}, {%8,%9}, {%0,%1,%2,%3};"
                 : "+f"(d0), "+f"(d1), "+f"(d2), "+f"(d3)
                 : "r"(a0), "r"(a1), "r"(a2), "r"(a3), "r"(b0), "r"(b1));
}
__device__ __forceinline__ void mma16816h(float& d0, float& d1, float& d2, float& d3,
                                          uint32_t a0, uint32_t a1, uint32_t a2, uint32_t a3,
                                          uint32_t b0, uint32_t b1) {
    asm volatile("mma.sync.aligned.m16n8k16.row.col.f32.f16.f16.f32 "
                 "{%0,%1,%2,%3}, {%4,%5,%6,%7}, {%8,%9}, {%0,%1,%2,%3};"
                 : "+f"(d0), "+f"(d1), "+f"(d2), "+f"(d3)
                 : "r"(a0), "r"(a1), "r"(a2), "r"(a3), "r"(b0), "r"(b1));
}

__device__ __forceinline__ float gelu_exact(float x) {
    return 0.5f * x * (1.0f + erff(x * 0.70710678118654752f));
}

// swizzled 64B-row offset: row r, 16B chunk c (0..3)
__device__ __forceinline__ uint32_t swz(uint32_t r, uint32_t c) {
    return r * 64 + ((c ^ ((r >> 1) & 3)) << 4);
}

// pack 4 floats into bf16 hi/lo pairs (8B each)
__device__ __forceinline__ void split4(float o0, float o1, float o2, float o3,
                                       uint2& hv, uint2& lv) {
    __nv_bfloat162 h01 = __floats2bfloat162_rn(o0, o1);
    __nv_bfloat162 h23 = __floats2bfloat162_rn(o2, o3);
    float e0 = o0 - __bfloat162float(h01.x), e1 = o1 - __bfloat162float(h01.y);
    float e2 = o2 - __bfloat162float(h23.x), e3 = o3 - __bfloat162float(h23.y);
    __nv_bfloat162 l01 = __floats2bfloat162_rn(e0, e1);
    __nv_bfloat162 l23 = __floats2bfloat162_rn(e2, e3);
    hv = make_uint2(*(uint32_t*)&h01, *(uint32_t*)&h23);
    lv = make_uint2(*(uint32_t*)&l01, *(uint32_t*)&l23);
}

// ---------------- TM64 HMMA GEMM (bf16x3): CTA 64x128, BK=32, 4-stage ----------------
// 8 warps (2x4) of 32x32 tiles. MODE 0: fp32 + bias. MODE 1: gelu + bf16 hi/lo.
// n1pass: CTAs whose columns lie below this bound use single-pass bf16 (hi only) —
// valid for precision-insensitive outputs (Q/K, whose contribution is ~1e-13 of att).
#define S64_AHI 0
#define S64_ALO 4096
#define S64_BHI 8192
#define S64_BLO 16384
#define STAGE64 24576
#define GEMM64_SMEM (4*STAGE64)

template<int MODE>
__global__ __launch_bounds__(256, 2)
void gemm_hmma64(const __nv_bfloat16* __restrict__ Ahi, const __nv_bfloat16* __restrict__ Alo,
                 const __nv_bfloat16* __restrict__ Bhi, const __nv_bfloat16* __restrict__ Blo,
                 const float* __restrict__ bias, float* __restrict__ C,
                 __nv_bfloat16* __restrict__ Chi, __nv_bfloat16* __restrict__ Clo,
                 int N, int K, int n1pass) {
    extern __shared__ char smem[];
    const uint32_t sb = smem_u32(smem);
    const int tid  = threadIdx.x;
    const int wid  = tid >> 5;
    const int lane = tid & 31;
    const int wrow = wid & 1;          // 32-row slab
    const int wcol = wid >> 1;         // 32-col slab
    const int bm = blockIdx.y << 6;
    const long bn = (long)blockIdx.x << 7;
    const int nc = K >> 5;
    const bool lite = (bn + 128 <= n1pass);

    const uint32_t rt = tid >> 2, ct = tid & 3;
    const uint32_t soA  = swz(rt, ct);
    const uint32_t soB1 = swz(rt + 64, ct);

    #define LOAD_FULL(kc, s) do {                                                      \
        uint32_t st_ = sb + (s) * STAGE64;                                              \
        size_t ga  = ((size_t)(bm + rt) * K + (kc) * 32 + ct * 8) * 2;                  \
        size_t gb0 = ((size_t)(bn + rt) * K + (kc) * 32 + ct * 8) * 2;                  \
        size_t gb1 = ((size_t)(bn + rt + 64) * K + (kc) * 32 + ct * 8) * 2;             \
        cp16(st_ + S64_AHI + soA,  (const char*)Ahi + ga);                              \
        cp16(st_ + S64_ALO + soA,  (const char*)Alo + ga);                              \
        cp16(st_ + S64_BHI + soA,  (const char*)Bhi + gb0);                             \
        cp16(st_ + S64_BLO + soA,  (const char*)Blo + gb0);                             \
        cp16(st_ + S64_BHI + soB1, (const char*)Bhi + gb1);                             \
        cp16(st_ + S64_BLO + soB1, (const char*)Blo + gb1);                             \
    } while (0)

    #define LOAD_LITE(kc, s) do {                                                      \
        uint32_t st_ = sb + (s) * STAGE64;                                              \
        size_t ga  = ((size_t)(bm + rt) * K + (kc) * 32 + ct * 8) * 2;                  \
        size_t gb0 = ((size_t)(bn + rt) * K + (kc) * 32 + ct * 8) * 2;                  \
        size_t gb1 = ((size_t)(bn + rt + 64) * K + (kc) * 32 + ct * 8) * 2;             \
        cp16(st_ + S64_AHI + soA,  (const char*)Ahi + ga);                              \
        cp16(st_ + S64_BHI + soA,  (const char*)Bhi + gb0);                             \
        cp16(st_ + S64_BHI + soB1, (const char*)Bhi + gb1);                             \
    } while (0)

    const int lane8 = lane & 7, sub = lane >> 3;
    const uint32_t ra = wrow * 32 + (sub & 1) * 8 + lane8;
    const uint32_t aks0 = swz(ra, (sub >> 1));
    const uint32_t aks1 = swz(ra, (sub >> 1) + 2);
    const uint32_t rb = wcol * 32 + lane8;
    const uint32_t boffs = swz(rb, sub);

    float acc[2][4][4];
    #pragma unroll
    for (int i = 0; i < 2; i++)
        #pragma unroll
        for (int j = 0; j < 4; j++)
            #pragma unroll
            for (int e = 0; e < 4; e++) acc[i][j][e] = 0.f;

    int slot = 0;
    if (!lite) {
        LOAD_FULL(0, 0); cp_commit();
        LOAD_FULL(1, 1); cp_commit();
        LOAD_FULL(2, 2); cp_commit();
        for (int it = 0; it < nc; it++) {
            cp_wait<2>();
            __syncthreads();
            if (it + 3 < nc) {
                int ns = slot + 3; if (ns >= 4) ns -= 4;
                LOAD_FULL(it + 3, ns);
            }
            cp_commit();
            const uint32_t st = sb + slot * STAGE64;

            uint32_t bh[4][4], bl[4][4], ah[2][2][4], al[2][2][4];
            #pragma unroll
            for (int nj = 0; nj < 4; nj++) {
                ldsm4(bh[nj][0], bh[nj][1], bh[nj][2], bh[nj][3], st + S64_BHI + boffs + nj * 512);
                ldsm4(bl[nj][0], bl[nj][1], bl[nj][2], bl[nj][3], st + S64_BLO + boffs + nj * 512);
            }
            #pragma unroll
            for (int mi = 0; mi < 2; mi++) {
                ldsm4(ah[0][mi][0], ah[0][mi][1], ah[0][mi][2], ah[0][mi][3],
                      st + S64_AHI + aks0 + mi * 1024);
                ldsm4(ah[1][mi][0], ah[1][mi][1], ah[1][mi][2], ah[1][mi][3],
                      st + S64_AHI + aks1 + mi * 1024);
                ldsm4(al[0][mi][0], al[0][mi][1], al[0][mi][2], al[0][mi][3],
                      st + S64_ALO + aks0 + mi * 1024);
                ldsm4(al[1][mi][0], al[1][mi][1], al[1][mi][2], al[1][mi][3],
                      st + S64_ALO + aks1 + mi * 1024);
            }
            #pragma unroll
            for (int ks = 0; ks < 2; ks++) {
                #pragma unroll
                for (int mi = 0; mi < 2; mi++)
                    #pragma unroll
                    for (int nj = 0; nj < 4; nj++)
                        mma16816(acc[mi][nj][0], acc[mi][nj][1], acc[mi][nj][2], acc[mi][nj][3],
                                 ah[ks][mi][0], ah[ks][mi][1], ah[ks][mi][2], ah[ks][mi][3],
                                 bh[nj][ks * 2], bh[nj][ks * 2 + 1]);
                #pragma unroll
                for (int mi = 0; mi < 2; mi++)
                    #pragma unroll
                    for (int nj = 0; nj < 4; nj++)
                        mma16816(acc[mi][nj][0], acc[mi][nj][1], acc[mi][nj][2], acc[mi][nj][3],
                                 ah[ks][mi][0], ah[ks][mi][1], ah[ks][mi][2], ah[ks][mi][3],
                                 bl[nj][ks * 2], bl[nj][ks * 2 + 1]);
                #pragma unroll
                for (int mi = 0; mi < 2; mi++)
                    #pragma unroll
                    for (int nj = 0; nj < 4; nj++)
                        mma16816(acc[mi][nj][0], acc[mi][nj][1], acc[mi][nj][2], acc[mi][nj][3],
                                 al[ks][mi][0], al[ks][mi][1], al[ks][mi][2], al[ks][mi][3],
                                 bh[nj][ks * 2], bh[nj][ks * 2 + 1]);
            }
            if (++slot == 4) slot = 0;
        }
    } else {
        LOAD_LITE(0, 0); cp_commit();
        LOAD_LITE(1, 1); cp_commit();
        LOAD_LITE(2, 2); cp_commit();
        for (int it = 0; it < nc; it++) {
            cp_wait<2>();
            __syncthreads();
            if (it + 3 < nc) {
                int ns = slot + 3; if (ns >= 4) ns -= 4;
                LOAD_LITE(it + 3, ns);
            }
            cp_commit();
            const uint32_t st = sb + slot * STAGE64;

            uint32_t bh[4][4], ah[2][2][4];
            #pragma unroll
            for (int nj = 0; nj < 4; nj++)
                ldsm4(bh[nj][0], bh[nj][1], bh[nj][2], bh[nj][3], st + S64_BHI + boffs + nj * 512);
            #pragma unroll
            for (int mi = 0; mi < 2; mi++) {
                ldsm4(ah[0][mi][0], ah[0][mi][1], ah[0][mi][2], ah[0][mi][3],
                      st + S64_AHI + aks0 + mi * 1024);
                ldsm4(ah[1][mi][0], ah[1][mi][1], ah[1][mi][2], ah[1][mi][3],
                      st + S64_AHI + aks1 + mi * 1024);
            }
            #pragma unroll
            for (int ks = 0; ks < 2; ks++)
                #pragma unroll
                for (int mi = 0; mi < 2; mi++)
                    #pragma unroll
                    for (int nj = 0; nj < 4; nj++)
                        mma16816(acc[mi][nj][0], acc[mi][nj][1], acc[mi][nj][2], acc[mi][nj][3],
                                 ah[ks][mi][0], ah[ks][mi][1], ah[ks][mi][2], ah[ks][mi][3],
                                 bh[nj][ks * 2], bh[nj][ks * 2 + 1]);
            if (++slot == 4) slot = 0;
        }
    }

    const int gr = lane >> 2;
    const int gc = (lane & 3) * 2;
    #pragma unroll
    for (int mi = 0; mi < 2; mi++) {
        size_t row0 = (size_t)(bm + wrow * 32 + mi * 16 + gr) * N;
        size_t row1 = row0 + (size_t)8 * N;
        #pragma unroll
        for (int nj = 0; nj < 4; nj++) {
            long c = bn + wcol * 32 + nj * 8 + gc;
            float b0 = bias[c], b1 = bias[c + 1];
            if (MODE == 0) {
                C[row0 + c]     = acc[mi][nj][0] + b0;
                C[row0 + c + 1] = acc[mi][nj][1] + b1;
                C[row1 + c]     = acc[mi][nj][2] + b0;
                C[row1 + c + 1] = acc[mi][nj][3] + b1;
            } else {
                float v0 = gelu_exact(acc[mi][nj][0] + b0);
                float v1 = gelu_exact(acc[mi][nj][1] + b1);
                float v2 = gelu_exact(acc[mi][nj][2] + b0);
                float v3 = gelu_exact(acc[mi][nj][3] + b1);
                __nv_bfloat162 hp0 = __floats2bfloat162_rn(v0, v1);
                __nv_bfloat162 hp1 = __floats2bfloat162_rn(v2, v3);
                float e0 = v0 - __bfloat162float(hp0.x), e1 = v1 - __bfloat162float(hp0.y);
                float e2 = v2 - __bfloat162float(hp1.x), e3 = v3 - __bfloat162float(hp1.y);
                __nv_bfloat162 lp0 = __floats2bfloat162_rn(e0, e1);
                __nv_bfloat162 lp1 = __floats2bfloat162_rn(e2, e3);
                *(uint32_t*)(Chi + row0 + c) = *(uint32_t*)&hp0;
                *(uint32_t*)(Clo + row0 + c) = *(uint32_t*)&lp0;
                *(uint32_t*)(Chi + row1 + c) = *(uint32_t*)&hp1;
                *(uint32_t*)(Clo + row1 + c) = *(uint32_t*)&lp1;
            }
        }
    }
    #undef LOAD_FULL
    #undef LOAD_LITE
}

// ---------------- fp16 single-term GEMM (LM head), 4-stage ----------------
#define F_TA 0
#define F_TB 8192
#define F_STAGE 16384
#define F16_SMEM (4*F_STAGE)

__global__ __launch_bounds__(256, 2)
void gemm_f16(const __half* __restrict__ A, const __half* __restrict__ B,
              const float* __restrict__ bias, float* __restrict__ C, int N, int K) {
    extern __shared__ char smem[];
    const uint32_t sb = smem_u32(smem);
    const int tid  = threadIdx.x;
    const int wid  = tid >> 5;
    const int lane = tid & 31;
    const int wrow = wid & 1;
    const int wcol = wid >> 1;
    const int bm = blockIdx.x << 7;
    const long bn = (long)blockIdx.y << 7;
    const int nc = K >> 5;

    const uint32_t r0t = tid >> 2, c0t = tid & 3;
    const uint32_t r1t = r0t + 64;
    const uint32_t so0 = swz(r0t, c0t);
    const uint32_t so1 = swz(r1t, c0t);

    #define LOAD_STAGE_F(kc, s) do {                                                   \
        uint32_t st_ = sb + (s) * F_STAGE;                                              \
        {                                                                               \
            size_t ga = ((size_t)(bm + r0t) * K + (kc) * 32 + c0t * 8) * 2;             \
            size_t gb = ((size_t)(bn + r0t) * K + (kc) * 32 + c0t * 8) * 2;             \
            cp16(st_ + F_TA + so0, (const char*)A + ga);                                \
            cp16(st_ + F_TB + so0, (const char*)B + gb);                                \
        }                                                                               \
        {                                                                               \
            size_t ga = ((size_t)(bm + r1t) * K + (kc) * 32 + c0t * 8) * 2;             \
            size_t gb = ((size_t)(bn + r1t) * K + (kc) * 32 + c0t * 8) * 2;             \
            cp16(st_ + F_TA + so1, (const char*)A + ga);                                \
            cp16(st_ + F_TB + so1, (const char*)B + gb);                                \
        }                                                                               \
    } while (0)

    LOAD_STAGE_F(0, 0); cp_commit();
    LOAD_STAGE_F(1, 1); cp_commit();
    LOAD_STAGE_F(2, 2); cp_commit();

    const int lane8 = lane & 7, sub = lane >> 3;
    const uint32_t ra = wrow * 64 + (sub & 1) * 8 + lane8;
    const uint32_t aks0 = swz(ra, (sub >> 1));
    const uint32_t aks1 = swz(ra, (sub >> 1) + 2);
    const uint32_t rb = wcol * 32 + lane8;
    const uint32_t boffs = swz(rb, sub);

    float acc[4][4][4];
    #pragma unroll
    for (int i = 0; i < 4; i++)
        #pragma unroll
        for (int j = 0; j < 4; j++)
            #pragma unroll
            for (int e = 0; e < 4; e++) acc[i][j][e] = 0.f;

    int slot = 0;
    for (int it = 0; it < nc; it++) {
        cp_wait<2>();
        __syncthreads();
        if (it + 3 < nc) {
            int ns = slot + 3; if (ns >= 4) ns -= 4;
            LOAD_STAGE_F(it + 3, ns);
        }
        cp_commit();
        const uint32_t st = sb + slot * F_STAGE;

        uint32_t bf[4][4];
        #pragma unroll
        for (int nj = 0; nj < 4; nj++)
            ldsm4(bf[nj][0], bf[nj][1], bf[nj][2], bf[nj][3], st + F_TB + boffs + nj * 512);
        #pragma unroll
        for (int ks = 0; ks < 2; ks++) {
            const uint32_t ao = (ks == 0) ? aks0 : aks1;
            uint32_t a[4][4];
            #pragma unroll
            for (int mi = 0; mi < 4; mi++)
                ldsm4(a[mi][0], a[mi][1], a[mi][2], a[mi][3], st + F_TA + ao + mi * 1024);
            #pragma unroll
            for (int mi = 0; mi < 4; mi++)
                #pragma unroll
                for (int nj = 0; nj < 4; nj++)
                    mma16816h(acc[mi][nj][0], acc[mi][nj][1], acc[mi][nj][2], acc[mi][nj][3],
                              a[mi][0], a[mi][1], a[mi][2], a[mi][3],
                              bf[nj][ks * 2], bf[nj][ks * 2 + 1]);
        }
        if (++slot == 4) slot = 0;
    }

    const int gr = lane >> 2;
    const int gc = (lane & 3) * 2;
    #pragma unroll
    for (int mi = 0; mi < 4; mi++) {
        size_t row0 = (size_t)(bm + wrow * 64 + mi * 16 + gr) * N;
        size_t row1 = row0 + (size_t)8 * N;
        #pragma unroll
        for (int nj = 0; nj < 4; nj++) {
            long c = bn + wcol * 32 + nj * 8 + gc;
            if (c < N) {
                C[row0 + c] = acc[mi][nj][0] + bias[c];
                C[row1 + c] = acc[mi][nj][2] + bias[c];
            }
            if (c + 1 < N) {
                C[row0 + c + 1] = acc[mi][nj][1] + bias[c + 1];
                C[row1 + c + 1] = acc[mi][nj][3] + bias[c + 1];
            }
        }
    }
    #undef LOAD_STAGE_F
}

// ---------------- weight transpose + split (bf16 hi/lo) ----------------
template<int QKV>
__global__ __launch_bounds__(256)
void transpose_split(const float* __restrict__ src0, const float* __restrict__ src1,
                     const float* __restrict__ src2,
                     __nv_bfloat16* __restrict__ hi, __nv_bfloat16* __restrict__ lo,
                     int R, int C) {
    __shared__ float t[128][33];
    int z = blockIdx.z;
    const float* src = src0;
    int sel = 0;
    if (QKV) {
        sel = z / (NLAYERS * NH);
        z   = z % (NLAYERS * NH);
        src = (sel == 0) ? src0 : (sel == 1) ? src1 : src2;
    }
    const size_t ib = (size_t)z * R * C;
    size_t ob;
    if (QKV) ob = (size_t)(z >> 4) * (3072 * 1024) + (size_t)sel * (1024 * 1024)
                + (size_t)(z & 15) * (64 * 1024);
    else     ob = ib;
    const int r0 = blockIdx.y * 128, c0 = blockIdx.x * 32;
    const int cc = threadIdx.x & 31, rb = threadIdx.x >> 5;
    const bool cok = (c0 + cc) < C;
    #pragma unroll
    for (int p = 0; p < 16; p++) {
        int rr = rb + p * 8;
        t[rr][cc] = cok ? src[ib + (size_t)(r0 + rr) * C + c0 + cc] : 0.f;
    }
    __syncthreads();
    const int oc = threadIdx.x >> 3, rq8 = threadIdx.x & 7;
    if (c0 + oc < C) {
        size_t obase = ob + (size_t)(c0 + oc) * R + r0;
        #pragma unroll
        for (int p = 0; p < 4; p++) {
            int r = (rq8 + p * 8) * 4;
            uint2 hv, lv;
            split4(t[r][oc], t[r + 1][oc], t[r + 2][oc], t[r + 3][oc], hv, lv);
            *(uint2*)(hi + obase + r) = hv;
            *(uint2*)(lo + obase + r) = lv;
        }
    }
}

// ---------------- fp16 weight transpose (LM head) ----------------
__global__ __launch_bounds__(256)
void transpose_f16(const float* __restrict__ src, __half* __restrict__ out, int R, int C) {
    __shared__ float t[128][33];
    const int r0 = blockIdx.y * 128, c0 = blockIdx.x * 32;
    const int cc = threadIdx.x & 31, rb = threadIdx.x >> 5;
    const bool cok = (c0 + cc) < C;
    #pragma unroll
    for (int p = 0; p < 16; p++) {
        int rr = rb + p * 8;
        t[rr][cc] = cok ? src[(size_t)(r0 + rr) * C + c0 + cc] : 0.f;
    }
    __syncthreads();
    const int oc = threadIdx.x >> 3, rq8 = threadIdx.x & 7;
    if (c0 + oc < C) {
        size_t obase = (size_t)(c0 + oc) * R + r0;
        #pragma unroll
        for (int p = 0; p < 4; p++) {
            int r = (rq8 + p * 8) * 4;
            __half2 h0 = __floats2half2_rn(t[r][oc], t[r + 1][oc]);
            __half2 h1 = __floats2half2_rn(t[r + 2][oc], t[r + 3][oc]);
            *(uint2*)(out + obase + r) = make_uint2(*(uint32_t*)&h0, *(uint32_t*)&h1);
        }
    }
}

// ---------------- embedding: x = emb[tok] + pos, + split ----------------
__global__ void embed_kernel(const int* __restrict__ tok, const float* __restrict__ emb,
                             const float* __restrict__ pos, float* __restrict__ x,
                             __nv_bfloat16* __restrict__ hi, __nv_bfloat16* __restrict__ lo) {
    int i4 = blockIdx.x * 256 + threadIdx.x;
    int e = i4 * 4;
    int s = e >> 10, h = e & 1023;
    float4 ev = *(const float4*)(emb + (size_t)tok[s] * H + h);
    float4 pv = *(const float4*)(pos + e);
    float o0 = ev.x + pv.x, o1 = ev.y + pv.y, o2 = ev.z + pv.z, o3 = ev.w + pv.w;
    *(float4*)(x + e) = make_float4(o0, o1, o2, o3);
    uint2 hv, lv;
    split4(o0, o1, o2, o3, hv, lv);
    *(uint2*)(hi + e) = hv;
    *(uint2*)(lo + e) = lv;
}

// ---------------- M_part = K^T V per (head, seg); 8 segs ----------------
__global__ __launch_bounds__(256)
void ktv_kernel(const float* __restrict__ qkv, float* __restrict__ mp) {
    const int head = blockIdx.x & 15, seg = blockIdx.x >> 4;   // seg 0..7
    __shared__ float Ks[64][65];
    __shared__ float Vs[64][65];
    const int tid = threadIdx.x;
    const int tr = tid >> 4, tc = tid & 15;
    float acc[4][4] = {};
    for (int t0 = seg * 256; t0 < seg * 256 + 256; t0 += 64) {
        for (int i = tid; i < 4096; i += 256) {
            int r = i >> 6, c = i & 63;
            size_t base = (size_t)(t0 + r) * 3072 + head * DH + c;
            Ks[r][c] = qkv[base + 1024];
            Vs[r][c] = qkv[base + 2048];
        }
        __syncthreads();
        #pragma unroll 4
        for (int t = 0; t < 64; t++) {
            float a[4], b[4];
            #pragma unroll
            for (int i = 0; i < 4; i++) a[i] = Ks[t][tr * 4 + i];
            #pragma unroll
            for (int j = 0; j < 4; j++) b[j] = Vs[t][tc * 4 + j];
            #pragma unroll
            for (int i = 0; i < 4; i++)
                #pragma unroll
                for (int j = 0; j < 4; j++)
                    acc[i][j] = fmaf(a[i], b[j], acc[i][j]);
        }
        __syncthreads();
    }
    #pragma unroll
    for (int i = 0; i < 4; i++)
        #pragma unroll
        for (int j = 0; j < 4; j++)
            mp[(size_t)(seg * 16 + head) * 4096 + (tr * 4 + i) * 64 + tc * 4 + j] = acc[i][j];
}

// ---------------- parallel suffix sum of V over S ----------------
__global__ void suf_partial(const float* __restrict__ qkv, float* __restrict__ part) {
    int col = blockIdx.y * 256 + threadIdx.x;
    int seg = blockIdx.x;
    float s = 0.f;
    for (int t = seg * 128; t < seg * 128 + 128; t++)
        s += qkv[(size_t)t * 3072 + 2048 + col];
    part[seg * 1024 + col] = s;
}
__global__ void suf_apply(const float* __restrict__ qkv, const float* __restrict__ part,
                          float* __restrict__ suf) {
    int col = blockIdx.y * 256 + threadIdx.x;
    int seg = blockIdx.x;
    float run = 0.f;
    for (int s2 = seg + 1; s2 < 16; s2++) run += part[s2 * 1024 + col];
    for (int t = seg * 128 + 127; t >= seg * 128; t--) {
        suf[(size_t)t * 1024 + col] = run;
        run += qkv[(size_t)t * 3072 + 2048 + col];
    }
}

// ---------------- attn = scale*(Q@M) - 1e9*suf, emit hi/lo split ----------------
__global__ __launch_bounds__(256)
void attn_combine(const float* __restrict__ qkv, const float* __restrict__ mp,
                  const float* __restrict__ suf,
                  __nv_bfloat16* __restrict__ ahi, __nv_bfloat16* __restrict__ alo) {
    const int head = blockIdx.y;
    const int s0 = blockIdx.x * 64;
    __shared__ float Qs[64][65];
    __shared__ float Ms[64][65];
    const int tid = threadIdx.x;
    for (int i = tid; i < 4096; i += 256) {
        int r = i >> 6, c = i & 63;
        Qs[r][c] = qkv[(size_t)(s0 + r) * 3072 + head * DH + c];
        float mv = 0.f;
        #pragma unroll
        for (int sg = 0; sg < 8; sg++) mv += mp[(size_t)(sg * 16 + head) * 4096 + i];
        Ms[r][c] = mv;
    }
    __syncthreads();
    const int tr = tid >> 4, tc = tid & 15;
    float acc[4][4] = {};
    #pragma unroll 4
    for (int hp = 0; hp < 64; hp++) {
        float a[4], b[4];
        #pragma unroll
        for (int i = 0; i < 4; i++) a[i] = Qs[tr * 4 + i][hp];
        #pragma unroll
        for (int j = 0; j < 4; j++) b[j] = Ms[hp][tc * 4 + j];
        #pragma unroll
        for (int i = 0; i < 4; i++)
            #pragma unroll
            for (int j = 0; j < 4; j++)
                acc[i][j] = fmaf(a[i], b[j], acc[i][j]);
    }
    #pragma unroll
    for (int i = 0; i < 4; i++) {
        int s = s0 + tr * 4 + i;
        size_t sb = (size_t)s * 1024 + head * DH + tc * 4;
        float o[4];
        #pragma unroll
        for (int j = 0; j < 4; j++)
            o[j] = 0.125f * acc[i][j] - 1e9f * suf[sb + j];
        uint2 hv, lv;
        split4(o[0], o[1], o[2], o[3], hv, lv);
        *(uint2*)(ahi + sb) = hv;
        *(uint2*)(alo + sb) = lv;
    }
}

// ---------------- LayerNorm (+residual) + fused split ----------------
template<bool ADD, bool WF32, int OUTK>
__global__ __launch_bounds__(256)
void ln_kernel(const float* __restrict__ t, const float* __restrict__ xin,
               const float* __restrict__ g, const float* __restrict__ b,
               float* __restrict__ outf,
               __nv_bfloat16* __restrict__ hi, __nv_bfloat16* __restrict__ lo,
               __half* __restrict__ outh) {
    const int row = blockIdx.x;
    const int tid = threadIdx.x;
    float4 v = *(const float4*)(t + (size_t)row * H + tid * 4);
    __shared__ float red[256];
    __shared__ float stat[2];

    float s = v.x + v.y + v.z + v.w;
    red[tid] = s; __syncthreads();
    for (int o = 128; o > 0; o >>= 1) {
        if (tid < o) red[tid] += red[tid + o];
        __syncthreads();
    }
    if (tid == 0) stat[0] = red[0] * (1.0f / H);
    __syncthreads();
    float mean = stat[0];

    float dx = v.x - mean, dy = v.y - mean, dz = v.z - mean, dw = v.w - mean;
    red[tid] = dx * dx + dy * dy + dz * dz + dw * dw; __syncthreads();
    for (int o = 128; o > 0; o >>= 1) {
        if (tid < o) red[tid] += red[tid + o];
        __syncthreads();
    }
    if (tid == 0) stat[1] = rsqrtf(red[0] * (1.0f / H) + 1e-5f);
    __syncthreads();
    float rstd = stat[1];

    int h = tid * 4;
    float4 gv = *(const float4*)(g + h);
    float4 bv = *(const float4*)(b + h);
    float o0 = dx * rstd * gv.x + bv.x;
    float o1 = dy * rstd * gv.y + bv.y;
    float o2 = dz * rstd * gv.z + bv.z;
    float o3 = dw * rstd * gv.w + bv.w;
    if (ADD) {
        float4 xv = *(const float4*)(xin + (size_t)row * H + h);
        o0 += xv.x; o1 += xv.y; o2 += xv.z; o3 += xv.w;
    }
    if (WF32) *(float4*)(outf + (size_t)row * H + h) = make_float4(o0, o1, o2, o3);
    if (OUTK == 0) {
        uint2 hv, lv;
        split4(o0, o1, o2, o3, hv, lv);
        *(uint2*)(hi + (size_t)row * H + h) = hv;
        *(uint2*)(lo + (size_t)row * H + h) = lv;
    } else {
        __half2 h0 = __floats2half2_rn(o0, o1);
        __half2 h1 = __floats2half2_rn(o2, o3);
        *(uint2*)(outh + (size_t)row * H + h) = make_uint2(*(uint32_t*)&h0, *(uint32_t*)&h1);
    }
}

// ---------------- launch ----------------
extern "C" void kernel_launch(void* const* d_in, const int* in_sizes, int n_in,
                              void* d_out, int out_size) {
    const int*   tokens = (const int*)  d_in[0];
    const float* emb    = (const float*)d_in[1];
    const float* pos    = (const float*)d_in[2];
    const float* Wq     = (const float*)d_in[3];
    const float* Wk     = (const float*)d_in[4];
    const float* Wv     = (const float*)d_in[5];
    const float* Wp     = (const float*)d_in[6];
    const float* bp     = (const float*)d_in[7];
    const float* W1     = (const float*)d_in[8];
    const float* b1     = (const float*)d_in[9];
    const float* W2     = (const float*)d_in[10];
    const float* b2     = (const float*)d_in[11];
    const float* ln_g   = (const float*)d_in[12];
    const float* ln_b   = (const float*)d_in[13];
    const float* Wlm    = (const float*)d_in[14];
    const float* blm    = (const float*)d_in[15];
    float* out = (float*)d_out;
    const int Vv = in_sizes[15];

    float *x, *tmp, *res, *qkv, *suf, *m, *part, *zb;
    __nv_bfloat16 *ahi, *alo, *bhi, *blo;
    __nv_bfloat16 *btqkv_hi, *btqkv_lo, *btp_hi, *btp_lo;
    __nv_bfloat16 *bt1_hi, *bt1_lo, *bt2_hi, *bt2_lo;
    __half *wlm, *xf16;
    cudaGetSymbolAddress((void**)&x, g_x);       cudaGetSymbolAddress((void**)&tmp, g_tmp);
    cudaGetSymbolAddress((void**)&res, g_res);   cudaGetSymbolAddress((void**)&qkv, g_qkv);
    cudaGetSymbolAddress((void**)&suf, g_suf);   cudaGetSymbolAddress((void**)&m, g_m);
    cudaGetSymbolAddress((void**)&part, g_part); cudaGetSymbolAddress((void**)&zb, g_zb);
    cudaGetSymbolAddress((void**)&ahi, g_ahi);   cudaGetSymbolAddress((void**)&alo, g_alo);
    cudaGetSymbolAddress((void**)&bhi, g_bhi);   cudaGetSymbolAddress((void**)&blo, g_blo);
    cudaGetSymbolAddress((void**)&btqkv_hi, g_btqkv_hi);
    cudaGetSymbolAddress((void**)&btqkv_lo, g_btqkv_lo);
    cudaGetSymbolAddress((void**)&btp_hi, g_btp_hi); cudaGetSymbolAddress((void**)&btp_lo, g_btp_lo);
    cudaGetSymbolAddress((void**)&bt1_hi, g_bt1_hi); cudaGetSymbolAddress((void**)&bt1_lo, g_bt1_lo);
    cudaGetSymbolAddress((void**)&bt2_hi, g_bt2_hi); cudaGetSymbolAddress((void**)&bt2_lo, g_bt2_lo);
    cudaGetSymbolAddress((void**)&wlm, g_wlm_f16);   cudaGetSymbolAddress((void**)&xf16, g_xf_f16);

    cudaFuncSetAttribute(gemm_hmma64<0>, cudaFuncAttributeMaxDynamicSharedMemorySize, GEMM64_SMEM);
    cudaFuncSetAttribute(gemm_hmma64<1>, cudaFuncAttributeMaxDynamicSharedMemorySize, GEMM64_SMEM);
    cudaFuncSetAttribute(gemm_f16, cudaFuncAttributeMaxDynamicSharedMemorySize, F16_SMEM);

    dim3 tb(256);
    // idx0: embed
    embed_kernel<<<(S * H) / 1024, 256>>>(tokens, emb, pos, x, ahi, alo);
    // idx1: combined qkv weight transpose (rows 0..1023=Q, 1024..2047=K, 2048..3071=V)
    transpose_split<1><<<dim3(2, 8, 3 * NLAYERS * NH), tb>>>(Wq, Wk, Wv,
                                                             btqkv_hi, btqkv_lo, H, DH);
    // idx2: proj weights
    transpose_split<0><<<dim3(32, 8, NLAYERS), tb>>>(Wp, nullptr, nullptr,
                                                     btp_hi, btp_lo, H, H);
    // idx3: QKV GEMM layer 0 (Q/K columns single-pass, V columns bf16x3)
    gemm_hmma64<0><<<dim3(24, 32), 256, GEMM64_SMEM>>>(ahi, alo, btqkv_hi, btqkv_lo,
                                                       zb, qkv, nullptr, nullptr, 3072, H, 2048);
    // remaining weight transposes
    transpose_split<0><<<dim3(128, 8, NLAYERS), tb>>>(W1, nullptr, nullptr, bt1_hi, bt1_lo, H, FF);
    transpose_split<0><<<dim3(32, 32, NLAYERS), tb>>>(W2, nullptr, nullptr, bt2_hi, bt2_lo, FF, H);
    transpose_f16<<<dim3((Vv + 31) / 32, 8), tb>>>(Wlm, wlm, H, Vv);

    for (int l = 0; l < NLAYERS; l++) {
        size_t oQ = (size_t)l * 3072 * H;
        size_t oH = (size_t)l * H * H;
        size_t oF = (size_t)l * H * FF;

        if (l > 0)
            gemm_hmma64<0><<<dim3(24, 32), 256, GEMM64_SMEM>>>(ahi, alo, btqkv_hi + oQ, btqkv_lo + oQ,
                                                               zb, qkv, nullptr, nullptr, 3072, H, 2048);
        ktv_kernel<<<128, 256>>>(qkv, m);
        suf_partial<<<dim3(16, 4), 256>>>(qkv, part);
        suf_apply<<<dim3(16, 4), 256>>>(qkv, part, suf);
        attn_combine<<<dim3(S / 64, NH), 256>>>(qkv, m, suf, ahi, alo);

        gemm_hmma64<0><<<dim3(8, 32), 256, GEMM64_SMEM>>>(ahi, alo, btp_hi + oH, btp_lo + oH,
                                                          bp + (size_t)l * H, tmp, nullptr, nullptr,
                                                          H, H, 0);
        ln_kernel<true, true, 0><<<S, 256>>>(tmp, x, ln_g, ln_b, res, ahi, alo, nullptr);

        gemm_hmma64<1><<<dim3(32, 32), 256, GEMM64_SMEM>>>(ahi, alo, bt1_hi + oF, bt1_lo + oF,
                                                           b1 + (size_t)l * FF, nullptr, bhi, blo,
                                                           FF, H, 0);
        gemm_hmma64<0><<<dim3(8, 32), 256, GEMM64_SMEM>>>(bhi, blo, bt2_hi + oF, bt2_lo + oF,
                                                          b2 + (size_t)l * H, tmp, nullptr, nullptr,
                                                          H, FF, 0);
        ln_kernel<true, true, 0><<<S, 256>>>(tmp, res, ln_g, ln_b, x, ahi, alo, nullptr);
    }

    // final LN -> fp16, LM head in fp16 HMMA
    ln_kernel<false, false, 1><<<S, 256>>>(x, nullptr, ln_g, ln_b, nullptr, nullptr, nullptr, xf16);
    gemm_f16<<<dim3(16, VPAD / 128), 256, F16_SMEM>>>(xf16, wlm, blm, out, Vv, H);
}

// round 11
// speedup vs baseline: 1.5074x; 1.0095x over previous
#include <cuda_runtime.h>
#include <cuda_bf16.h>
#include <cuda_fp16.h>
#include <math.h>
#include <stdint.h>

#define S  2048
#define H  1024
#define NH 16
#define DH 64
#define FF 4096
#define NLAYERS 6
#define VPAD 50432     // 50257 padded to multiple of 128

#define SZ_SH (S*H)

// ---------------- device scratch ----------------
__device__ __align__(16) float g_x[SZ_SH];
__device__ __align__(16) float g_tmp[SZ_SH];
__device__ __align__(16) float g_res[SZ_SH];
__device__ __align__(16) float g_qkv[S*3072];
__device__ __align__(16) float g_suf[SZ_SH];
__device__ __align__(16) float g_m[16*NH*DH*DH];    // split-K partials (16 segs)
__device__ __align__(16) float g_part[16*1024];
__device__ __align__(16) float g_zb[8192];          // zero bias (never written)

// activation hi/lo
__device__ __align__(128) __nv_bfloat16 g_ahi[S*FF];
__device__ __align__(128) __nv_bfloat16 g_alo[S*FF];
__device__ __align__(128) __nv_bfloat16 g_bhi[S*FF];
__device__ __align__(128) __nv_bfloat16 g_blo[S*FF];

// weight hi/lo, K-major transposed [N,K]
__device__ __align__(128) __nv_bfloat16 g_btqkv_hi[NLAYERS*3072*H];
__device__ __align__(128) __nv_bfloat16 g_btqkv_lo[NLAYERS*3072*H];
__device__ __align__(128) __nv_bfloat16 g_btp_hi[NLAYERS*H*H];
__device__ __align__(128) __nv_bfloat16 g_btp_lo[NLAYERS*H*H];
__device__ __align__(128) __nv_bfloat16 g_bt1_hi[NLAYERS*H*FF];
__device__ __align__(128) __nv_bfloat16 g_bt1_lo[NLAYERS*H*FF];
__device__ __align__(128) __nv_bfloat16 g_bt2_hi[NLAYERS*H*FF];
__device__ __align__(128) __nv_bfloat16 g_bt2_lo[NLAYERS*H*FF];
__device__ __align__(128) __half g_wlm_f16[VPAD*H];  // fp16 LM weights, pad rows stay zero
__device__ __align__(128) __half g_xf_f16[SZ_SH];    // fp16 final-LN activations

// ---------------- PTX helpers ----------------
__device__ __forceinline__ uint32_t smem_u32(const void* p) {
    uint32_t a;
    asm("{ .reg .u64 t; cvta.to.shared.u64 t, %1; cvt.u32.u64 %0, t; }" : "=r"(a) : "l"(p));
    return a;
}
__device__ __forceinline__ void cp16(uint32_t dst, const void* src) {
    asm volatile("cp.async.cg.shared.global [%0], [%1], 16;" :: "r"(dst), "l"(src));
}
__device__ __forceinline__ void cp_commit() { asm volatile("cp.async.commit_group;" ::: "memory"); }
template<int N> __device__ __forceinline__ void cp_wait() {
    asm volatile("cp.async.wait_group %0;" :: "n"(N) : "memory");
}
__device__ __forceinline__ void ldsm4(uint32_t& r0, uint32_t& r1, uint32_t& r2, uint32_t& r3,
                                      uint32_t addr) {
    asm volatile("ldmatrix.sync.aligned.m8n8.x4.shared.b16 {%0,%1,%2,%3}, [%4];"
                 : "=r"(r0), "=r"(r1), "=r"(r2), "=r"(r3) : "r"(addr));
}
__device__ __forceinline__ void mma16816(float& d0, float& d1, float& d2, float& d3,
                                         uint32_t a0, uint32_t a1, uint32_t a2, uint32_t a3,
                                         uint32_t b0, uint32_t b1) {
    asm volatile("mma.sync.aligned.m16n8k16.row.col.f32.bf16.bf16.f32 "
                 "{%0,%1,%2,%3}, {%4,%5,%6,%7}, {%8,%9}, {%0,%1,%2,%3};"
                 : "+f"(d0), "+f"(d1), "+f"(d2), "+f"(d3)
                 : "r"(a0), "r"(a1), "r"(a2), "r"(a3), "r"(b0), "r"(b1));
}
__device__ __forceinline__ void mma16816h(float& d0, float& d1, float& d2, float& d3,
                                          uint32_t a0, uint32_t a1, uint32_t a2, uint32_t a3,
                                          uint32_t b0, uint32_t b1) {
    asm volatile("mma.sync.aligned.m16n8k16.row.col.f32.f16.f16.f32 "
                 "{%0,%1,%2,%3}, {%4,%5,%6,%7}, {%8,%9}, {%0,%1,%2,%3};"
                 : "+f"(d0), "+f"(d1), "+f"(d2), "+f"(d3)
                 : "r"(a0), "r"(a1), "r"(a2), "r"(a3), "r"(b0), "r"(b1));
}

__device__ __forceinline__ float gelu_exact(float x) {
    return 0.5f * x * (1.0f + erff(x * 0.70710678118654752f));
}

// swizzled 64B-row offset: row r, 16B chunk c (0..3)
__device__ __forceinline__ uint32_t swz(uint32_t r, uint32_t c) {
    return r * 64 + ((c ^ ((r >> 1) & 3)) << 4);
}

// pack 4 floats into bf16 hi/lo pairs (8B each)
__device__ __forceinline__ void split4(float o0, float o1, float o2, float o3,
                                       uint2& hv, uint2& lv) {
    __nv_bfloat162 h01 = __floats2bfloat162_rn(o0, o1);
    __nv_bfloat162 h23 = __floats2bfloat162_rn(o2, o3);
    float e0 = o0 - __bfloat162float(h01.x), e1 = o1 - __bfloat162float(h01.y);
    float e2 = o2 - __bfloat162float(h23.x), e3 = o3 - __bfloat162float(h23.y);
    __nv_bfloat162 l01 = __floats2bfloat162_rn(e0, e1);
    __nv_bfloat162 l23 = __floats2bfloat162_rn(e2, e3);
    hv = make_uint2(*(uint32_t*)&h01, *(uint32_t*)&h23);
    lv = make_uint2(*(uint32_t*)&l01, *(uint32_t*)&l23);
}

// ---------------- TM64 HMMA GEMM (bf16x3): CTA 64x128, BK=32, 4-stage ----------------
// 8 warps (2x4) of 32x32 tiles. MODE 0: fp32 + bias. MODE 1: gelu + bf16 hi/lo.
// n1pass: CTAs whose columns lie below this bound use single-pass bf16 (hi only).
#define S64_AHI 0
#define S64_ALO 4096
#define S64_BHI 8192
#define S64_BLO 16384
#define STAGE64 24576
#define GEMM64_SMEM (4*STAGE64)

template<int MODE>
__global__ __launch_bounds__(256, 2)
void gemm_hmma64(const __nv_bfloat16* __restrict__ Ahi, const __nv_bfloat16* __restrict__ Alo,
                 const __nv_bfloat16* __restrict__ Bhi, const __nv_bfloat16* __restrict__ Blo,
                 const float* __restrict__ bias, float* __restrict__ C,
                 __nv_bfloat16* __restrict__ Chi, __nv_bfloat16* __restrict__ Clo,
                 int N, int K, int n1pass) {
    extern __shared__ char smem[];
    const uint32_t sb = smem_u32(smem);
    const int tid  = threadIdx.x;
    const int wid  = tid >> 5;
    const int lane = tid & 31;
    const int wrow = wid & 1;
    const int wcol = wid >> 1;
    const int bm = blockIdx.y << 6;
    const long bn = (long)blockIdx.x << 7;
    const int nc = K >> 5;
    const bool lite = (bn + 128 <= n1pass);

    const uint32_t rt = tid >> 2, ct = tid & 3;
    const uint32_t soA  = swz(rt, ct);
    const uint32_t soB1 = swz(rt + 64, ct);

    #define LOAD_FULL(kc, s) do {                                                      \
        uint32_t st_ = sb + (s) * STAGE64;                                              \
        size_t ga  = ((size_t)(bm + rt) * K + (kc) * 32 + ct * 8) * 2;                  \
        size_t gb0 = ((size_t)(bn + rt) * K + (kc) * 32 + ct * 8) * 2;                  \
        size_t gb1 = ((size_t)(bn + rt + 64) * K + (kc) * 32 + ct * 8) * 2;             \
        cp16(st_ + S64_AHI + soA,  (const char*)Ahi + ga);                              \
        cp16(st_ + S64_ALO + soA,  (const char*)Alo + ga);                              \
        cp16(st_ + S64_BHI + soA,  (const char*)Bhi + gb0);                             \
        cp16(st_ + S64_BLO + soA,  (const char*)Blo + gb0);                             \
        cp16(st_ + S64_BHI + soB1, (const char*)Bhi + gb1);                             \
        cp16(st_ + S64_BLO + soB1, (const char*)Blo + gb1);                             \
    } while (0)

    #define LOAD_LITE(kc, s) do {                                                      \
        uint32_t st_ = sb + (s) * STAGE64;                                              \
        size_t ga  = ((size_t)(bm + rt) * K + (kc) * 32 + ct * 8) * 2;                  \
        size_t gb0 = ((size_t)(bn + rt) * K + (kc) * 32 + ct * 8) * 2;                  \
        size_t gb1 = ((size_t)(bn + rt + 64) * K + (kc) * 32 + ct * 8) * 2;             \
        cp16(st_ + S64_AHI + soA,  (const char*)Ahi + ga);                              \
        cp16(st_ + S64_BHI + soA,  (const char*)Bhi + gb0);                             \
        cp16(st_ + S64_BHI + soB1, (const char*)Bhi + gb1);                             \
    } while (0)

    const int lane8 = lane & 7, sub = lane >> 3;
    const uint32_t ra = wrow * 32 + (sub & 1) * 8 + lane8;
    const uint32_t aks0 = swz(ra, (sub >> 1));
    const uint32_t aks1 = swz(ra, (sub >> 1) + 2);
    const uint32_t rb = wcol * 32 + lane8;
    const uint32_t boffs = swz(rb, sub);

    float acc[2][4][4];
    #pragma unroll
    for (int i = 0; i < 2; i++)
        #pragma unroll
        for (int j = 0; j < 4; j++)
            #pragma unroll
            for (int e = 0; e < 4; e++) acc[i][j][e] = 0.f;

    int slot = 0;
    if (!lite) {
        LOAD_FULL(0, 0); cp_commit();
        LOAD_FULL(1, 1); cp_commit();
        LOAD_FULL(2, 2); cp_commit();
        for (int it = 0; it < nc; it++) {
            cp_wait<2>();
            __syncthreads();
            if (it + 3 < nc) {
                int ns = slot + 3; if (ns >= 4) ns -= 4;
                LOAD_FULL(it + 3, ns);
            }
            cp_commit();
            const uint32_t st = sb + slot * STAGE64;

            uint32_t bh[4][4], bl[4][4], ah[2][2][4], al[2][2][4];
            #pragma unroll
            for (int nj = 0; nj < 4; nj++) {
                ldsm4(bh[nj][0], bh[nj][1], bh[nj][2], bh[nj][3], st + S64_BHI + boffs + nj * 512);
                ldsm4(bl[nj][0], bl[nj][1], bl[nj][2], bl[nj][3], st + S64_BLO + boffs + nj * 512);
            }
            #pragma unroll
            for (int mi = 0; mi < 2; mi++) {
                ldsm4(ah[0][mi][0], ah[0][mi][1], ah[0][mi][2], ah[0][mi][3],
                      st + S64_AHI + aks0 + mi * 1024);
                ldsm4(ah[1][mi][0], ah[1][mi][1], ah[1][mi][2], ah[1][mi][3],
                      st + S64_AHI + aks1 + mi * 1024);
                ldsm4(al[0][mi][0], al[0][mi][1], al[0][mi][2], al[0][mi][3],
                      st + S64_ALO + aks0 + mi * 1024);
                ldsm4(al[1][mi][0], al[1][mi][1], al[1][mi][2], al[1][mi][3],
                      st + S64_ALO + aks1 + mi * 1024);
            }
            #pragma unroll
            for (int ks = 0; ks < 2; ks++) {
                #pragma unroll
                for (int mi = 0; mi < 2; mi++)
                    #pragma unroll
                    for (int nj = 0; nj < 4; nj++)
                        mma16816(acc[mi][nj][0], acc[mi][nj][1], acc[mi][nj][2], acc[mi][nj][3],
                                 ah[ks][mi][0], ah[ks][mi][1], ah[ks][mi][2], ah[ks][mi][3],
                                 bh[nj][ks * 2], bh[nj][ks * 2 + 1]);
                #pragma unroll
                for (int mi = 0; mi < 2; mi++)
                    #pragma unroll
                    for (int nj = 0; nj < 4; nj++)
                        mma16816(acc[mi][nj][0], acc[mi][nj][1], acc[mi][nj][2], acc[mi][nj][3],
                                 ah[ks][mi][0], ah[ks][mi][1], ah[ks][mi][2], ah[ks][mi][3],
                                 bl[nj][ks * 2], bl[nj][ks * 2 + 1]);
                #pragma unroll
                for (int mi = 0; mi < 2; mi++)
                    #pragma unroll
                    for (int nj = 0; nj < 4; nj++)
                        mma16816(acc[mi][nj][0], acc[mi][nj][1], acc[mi][nj][2], acc[mi][nj][3],
                                 al[ks][mi][0], al[ks][mi][1], al[ks][mi][2], al[ks][mi][3],
                                 bh[nj][ks * 2], bh[nj][ks * 2 + 1]);
            }
            if (++slot == 4) slot = 0;
        }
    } else {
        LOAD_LITE(0, 0); cp_commit();
        LOAD_LITE(1, 1); cp_commit();
        LOAD_LITE(2, 2); cp_commit();
        for (int it = 0; it < nc; it++) {
            cp_wait<2>();
            __syncthreads();
            if (it + 3 < nc) {
                int ns = slot + 3; if (ns >= 4) ns -= 4;
                LOAD_LITE(it + 3, ns);
            }
            cp_commit();
            const uint32_t st = sb + slot * STAGE64;

            uint32_t bh[4][4], ah[2][2][4];
            #pragma unroll
            for (int nj = 0; nj < 4; nj++)
                ldsm4(bh[nj][0], bh[nj][1], bh[nj][2], bh[nj][3], st + S64_BHI + boffs + nj * 512);
            #pragma unroll
            for (int mi = 0; mi < 2; mi++) {
                ldsm4(ah[0][mi][0], ah[0][mi][1], ah[0][mi][2], ah[0][mi][3],
                      st + S64_AHI + aks0 + mi * 1024);
                ldsm4(ah[1][mi][0], ah[1][mi][1], ah[1][mi][2], ah[1][mi][3],
                      st + S64_AHI + aks1 + mi * 1024);
            }
            #pragma unroll
            for (int ks = 0; ks < 2; ks++)
                #pragma unroll
                for (int mi = 0; mi < 2; mi++)
                    #pragma unroll
                    for (int nj = 0; nj < 4; nj++)
                        mma16816(acc[mi][nj][0], acc[mi][nj][1], acc[mi][nj][2], acc[mi][nj][3],
                                 ah[ks][mi][0], ah[ks][mi][1], ah[ks][mi][2], ah[ks][mi][3],
                                 bh[nj][ks * 2], bh[nj][ks * 2 + 1]);
            if (++slot == 4) slot = 0;
        }
    }

    const int gr = lane >> 2;
    const int gc = (lane & 3) * 2;
    #pragma unroll
    for (int mi = 0; mi < 2; mi++) {
        size_t row0 = (size_t)(bm + wrow * 32 + mi * 16 + gr) * N;
        size_t row1 = row0 + (size_t)8 * N;
        #pragma unroll
        for (int nj = 0; nj < 4; nj++) {
            long c = bn + wcol * 32 + nj * 8 + gc;
            float b0 = bias[c], b1 = bias[c + 1];
            if (MODE == 0) {
                C[row0 + c]     = acc[mi][nj][0] + b0;
                C[row0 + c + 1] = acc[mi][nj][1] + b1;
                C[row1 + c]     = acc[mi][nj][2] + b0;
                C[row1 + c + 1] = acc[mi][nj][3] + b1;
            } else {
                float v0 = gelu_exact(acc[mi][nj][0] + b0);
                float v1 = gelu_exact(acc[mi][nj][1] + b1);
                float v2 = gelu_exact(acc[mi][nj][2] + b0);
                float v3 = gelu_exact(acc[mi][nj][3] + b1);
                __nv_bfloat162 hp0 = __floats2bfloat162_rn(v0, v1);
                __nv_bfloat162 hp1 = __floats2bfloat162_rn(v2, v3);
                float e0 = v0 - __bfloat162float(hp0.x), e1 = v1 - __bfloat162float(hp0.y);
                float e2 = v2 - __bfloat162float(hp1.x), e3 = v3 - __bfloat162float(hp1.y);
                __nv_bfloat162 lp0 = __floats2bfloat162_rn(e0, e1);
                __nv_bfloat162 lp1 = __floats2bfloat162_rn(e2, e3);
                *(uint32_t*)(Chi + row0 + c) = *(uint32_t*)&hp0;
                *(uint32_t*)(Clo + row0 + c) = *(uint32_t*)&lp0;
                *(uint32_t*)(Chi + row1 + c) = *(uint32_t*)&hp1;
                *(uint32_t*)(Clo + row1 + c) = *(uint32_t*)&lp1;
            }
        }
    }
    #undef LOAD_FULL
    #undef LOAD_LITE
}

// ---------------- fp16 single-term GEMM (LM head), 4-stage ----------------
#define F_TA 0
#define F_TB 8192
#define F_STAGE 16384
#define F16_SMEM (4*F_STAGE)

__global__ __launch_bounds__(256, 2)
void gemm_f16(const __half* __restrict__ A, const __half* __restrict__ B,
              const float* __restrict__ bias, float* __restrict__ C, int N, int K) {
    extern __shared__ char smem[];
    const uint32_t sb = smem_u32(smem);
    const int tid  = threadIdx.x;
    const int wid  = tid >> 5;
    const int lane = tid & 31;
    const int wrow = wid & 1;
    const int wcol = wid >> 1;
    const int bm = blockIdx.x << 7;
    const long bn = (long)blockIdx.y << 7;
    const int nc = K >> 5;

    const uint32_t r0t = tid >> 2, c0t = tid & 3;
    const uint32_t r1t = r0t + 64;
    const uint32_t so0 = swz(r0t, c0t);
    const uint32_t so1 = swz(r1t, c0t);

    #define LOAD_STAGE_F(kc, s) do {                                                   \
        uint32_t st_ = sb + (s) * F_STAGE;                                              \
        {                                                                               \
            size_t ga = ((size_t)(bm + r0t) * K + (kc) * 32 + c0t * 8) * 2;             \
            size_t gb = ((size_t)(bn + r0t) * K + (kc) * 32 + c0t * 8) * 2;             \
            cp16(st_ + F_TA + so0, (const char*)A + ga);                                \
            cp16(st_ + F_TB + so0, (const char*)B + gb);                                \
        }                                                                               \
        {                                                                               \
            size_t ga = ((size_t)(bm + r1t) * K + (kc) * 32 + c0t * 8) * 2;             \
            size_t gb = ((size_t)(bn + r1t) * K + (kc) * 32 + c0t * 8) * 2;             \
            cp16(st_ + F_TA + so1, (const char*)A + ga);                                \
            cp16(st_ + F_TB + so1, (const char*)B + gb);                                \
        }                                                                               \
    } while (0)

    LOAD_STAGE_F(0, 0); cp_commit();
    LOAD_STAGE_F(1, 1); cp_commit();
    LOAD_STAGE_F(2, 2); cp_commit();

    const int lane8 = lane & 7, sub = lane >> 3;
    const uint32_t ra = wrow * 64 + (sub & 1) * 8 + lane8;
    const uint32_t aks0 = swz(ra, (sub >> 1));
    const uint32_t aks1 = swz(ra, (sub >> 1) + 2);
    const uint32_t rb = wcol * 32 + lane8;
    const uint32_t boffs = swz(rb, sub);

    float acc[4][4][4];
    #pragma unroll
    for (int i = 0; i < 4; i++)
        #pragma unroll
        for (int j = 0; j < 4; j++)
            #pragma unroll
            for (int e = 0; e < 4; e++) acc[i][j][e] = 0.f;

    int slot = 0;
    for (int it = 0; it < nc; it++) {
        cp_wait<2>();
        __syncthreads();
        if (it + 3 < nc) {
            int ns = slot + 3; if (ns >= 4) ns -= 4;
            LOAD_STAGE_F(it + 3, ns);
        }
        cp_commit();
        const uint32_t st = sb + slot * F_STAGE;

        uint32_t bf[4][4];
        #pragma unroll
        for (int nj = 0; nj < 4; nj++)
            ldsm4(bf[nj][0], bf[nj][1], bf[nj][2], bf[nj][3], st + F_TB + boffs + nj * 512);
        #pragma unroll
        for (int ks = 0; ks < 2; ks++) {
            const uint32_t ao = (ks == 0) ? aks0 : aks1;
            uint32_t a[4][4];
            #pragma unroll
            for (int mi = 0; mi < 4; mi++)
                ldsm4(a[mi][0], a[mi][1], a[mi][2], a[mi][3], st + F_TA + ao + mi * 1024);
            #pragma unroll
            for (int mi = 0; mi < 4; mi++)
                #pragma unroll
                for (int nj = 0; nj < 4; nj++)
                    mma16816h(acc[mi][nj][0], acc[mi][nj][1], acc[mi][nj][2], acc[mi][nj][3],
                              a[mi][0], a[mi][1], a[mi][2], a[mi][3],
                              bf[nj][ks * 2], bf[nj][ks * 2 + 1]);
        }
        if (++slot == 4) slot = 0;
    }

    const int gr = lane >> 2;
    const int gc = (lane & 3) * 2;
    #pragma unroll
    for (int mi = 0; mi < 4; mi++) {
        size_t row0 = (size_t)(bm + wrow * 64 + mi * 16 + gr) * N;
        size_t row1 = row0 + (size_t)8 * N;
        #pragma unroll
        for (int nj = 0; nj < 4; nj++) {
            long c = bn + wcol * 32 + nj * 8 + gc;
            if (c < N) {
                C[row0 + c] = acc[mi][nj][0] + bias[c];
                C[row1 + c] = acc[mi][nj][2] + bias[c];
            }
            if (c + 1 < N) {
                C[row0 + c + 1] = acc[mi][nj][1] + bias[c + 1];
                C[row1 + c + 1] = acc[mi][nj][3] + bias[c + 1];
            }
        }
    }
    #undef LOAD_STAGE_F
}

// ---------------- weight transpose + split (bf16 hi/lo), 16B stores ----------------
// QKV=1: z major selects q/k/v source; lo plane skipped for Q/K (lite path never reads it).
template<int QKV>
__global__ __launch_bounds__(256)
void transpose_split(const float* __restrict__ src0, const float* __restrict__ src1,
                     const float* __restrict__ src2,
                     __nv_bfloat16* __restrict__ hi, __nv_bfloat16* __restrict__ lo,
                     int R, int C) {
    __shared__ float t[128][33];
    int z = blockIdx.z;
    const float* src = src0;
    int sel = 0;
    if (QKV) {
        sel = z / (NLAYERS * NH);
        z   = z % (NLAYERS * NH);
        src = (sel == 0) ? src0 : (sel == 1) ? src1 : src2;
    }
    const size_t ib = (size_t)z * R * C;
    size_t ob;
    if (QKV) ob = (size_t)(z >> 4) * (3072 * 1024) + (size_t)sel * (1024 * 1024)
                + (size_t)(z & 15) * (64 * 1024);
    else     ob = ib;
    const int r0 = blockIdx.y * 128, c0 = blockIdx.x * 32;
    const int cc = threadIdx.x & 31, rb = threadIdx.x >> 5;
    const bool cok = (c0 + cc) < C;
    #pragma unroll
    for (int p = 0; p < 16; p++) {
        int rr = rb + p * 8;
        t[rr][cc] = cok ? src[ib + (size_t)(r0 + rr) * C + c0 + cc] : 0.f;
    }
    __syncthreads();
    const int oc2 = threadIdx.x >> 4;        // 0..15
    const int r8  = (threadIdx.x & 15) * 8;  // 0..120
    const bool wlo = (!QKV) || (sel == 2);
    #pragma unroll
    for (int cp = 0; cp < 2; cp++) {
        int col = cp * 16 + oc2;
        if (c0 + col < C) {
            uint32_t hw[4], lw[4];
            #pragma unroll
            for (int i = 0; i < 4; i++) {
                float f0 = t[r8 + 2 * i][col], f1 = t[r8 + 2 * i + 1][col];
                __nv_bfloat162 hp = __floats2bfloat162_rn(f0, f1);
                hw[i] = *(uint32_t*)&hp;
                float e0 = f0 - __bfloat162float(hp.x);
                float e1 = f1 - __bfloat162float(hp.y);
                __nv_bfloat162 lp = __floats2bfloat162_rn(e0, e1);
                lw[i] = *(uint32_t*)&lp;
            }
            size_t obase = ob + (size_t)(c0 + col) * R + r0 + r8;
            *(uint4*)(hi + obase) = make_uint4(hw[0], hw[1], hw[2], hw[3]);
            if (wlo) *(uint4*)(lo + obase) = make_uint4(lw[0], lw[1], lw[2], lw[3]);
        }
    }
}

// ---------------- fp16 weight transpose (LM head), 16B stores ----------------
__global__ __launch_bounds__(256)
void transpose_f16(const float* __restrict__ src, __half* __restrict__ out, int R, int C) {
    __shared__ float t[128][33];
    const int r0 = blockIdx.y * 128, c0 = blockIdx.x * 32;
    const int cc = threadIdx.x & 31, rb = threadIdx.x >> 5;
    const bool cok = (c0 + cc) < C;
    #pragma unroll
    for (int p = 0; p < 16; p++) {
        int rr = rb + p * 8;
        t[rr][cc] = cok ? src[(size_t)(r0 + rr) * C + c0 + cc] : 0.f;
    }
    __syncthreads();
    const int oc2 = threadIdx.x >> 4;
    const int r8  = (threadIdx.x & 15) * 8;
    #pragma unroll
    for (int cp = 0; cp < 2; cp++) {
        int col = cp * 16 + oc2;
        if (c0 + col < C) {
            uint32_t hw[4];
            #pragma unroll
            for (int i = 0; i < 4; i++) {
                __half2 hp = __floats2half2_rn(t[r8 + 2 * i][col], t[r8 + 2 * i + 1][col]);
                hw[i] = *(uint32_t*)&hp;
            }
            size_t obase = (size_t)(c0 + col) * R + r0 + r8;
            *(uint4*)(out + obase) = make_uint4(hw[0], hw[1], hw[2], hw[3]);
        }
    }
}

// ---------------- embedding: x = emb[tok] + pos, + split ----------------
__global__ void embed_kernel(const int* __restrict__ tok, const float* __restrict__ emb,
                             const float* __restrict__ pos, float* __restrict__ x,
                             __nv_bfloat16* __restrict__ hi, __nv_bfloat16* __restrict__ lo) {
    int i4 = blockIdx.x * 256 + threadIdx.x;
    int e = i4 * 4;
    int s = e >> 10, h = e & 1023;
    float4 ev = *(const float4*)(emb + (size_t)tok[s] * H + h);
    float4 pv = *(const float4*)(pos + e);
    float o0 = ev.x + pv.x, o1 = ev.y + pv.y, o2 = ev.z + pv.z, o3 = ev.w + pv.w;
    *(float4*)(x + e) = make_float4(o0, o1, o2, o3);
    uint2 hv, lv;
    split4(o0, o1, o2, o3, hv, lv);
    *(uint2*)(hi + e) = hv;
    *(uint2*)(lo + e) = lv;
}

// ---------------- fused: M_part = K^T V per (head, seg) + V column sums; 16 segs ----------------
__global__ __launch_bounds__(256)
void ktv_kernel(const float* __restrict__ qkv, float* __restrict__ mp,
                float* __restrict__ part) {
    const int head = blockIdx.x & 15, seg = blockIdx.x >> 4;   // seg 0..15
    __shared__ float Ks[64][65];
    __shared__ float Vs[64][65];
    __shared__ float red[4][64];
    const int tid = threadIdx.x;
    const int tr = tid >> 4, tc = tid & 15;
    const int vc = tid & 63, rg = tid >> 6;   // column + row-group for V sums
    float acc[4][4] = {};
    float csum = 0.f;
    for (int t0 = seg * 128; t0 < seg * 128 + 128; t0 += 64) {
        for (int i = tid; i < 4096; i += 256) {
            int r = i >> 6, c = i & 63;
            size_t base = (size_t)(t0 + r) * 3072 + head * DH + c;
            Ks[r][c] = qkv[base + 1024];
            Vs[r][c] = qkv[base + 2048];
        }
        __syncthreads();
        #pragma unroll 4
        for (int t = 0; t < 64; t++) {
            float a[4], b[4];
            #pragma unroll
            for (int i = 0; i < 4; i++) a[i] = Ks[t][tr * 4 + i];
            #pragma unroll
            for (int j = 0; j < 4; j++) b[j] = Vs[t][tc * 4 + j];
            #pragma unroll
            for (int i = 0; i < 4; i++)
                #pragma unroll
                for (int j = 0; j < 4; j++)
                    acc[i][j] = fmaf(a[i], b[j], acc[i][j]);
        }
        // V column partial sums from the tile already in smem
        #pragma unroll
        for (int r = 0; r < 16; r++) csum += Vs[rg * 16 + r][vc];
        __syncthreads();
    }
    red[rg][vc] = csum;
    __syncthreads();
    if (tid < 64)
        part[seg * 1024 + head * 64 + tid] =
            red[0][tid] + red[1][tid] + red[2][tid] + red[3][tid];
    #pragma unroll
    for (int i = 0; i < 4; i++)
        #pragma unroll
        for (int j = 0; j < 4; j++)
            mp[(size_t)(seg * 16 + head) * 4096 + (tr * 4 + i) * 64 + tc * 4 + j] = acc[i][j];
}

// ---------------- suffix apply (uses part from ktv) ----------------
__global__ void suf_apply(const float* __restrict__ qkv, const float* __restrict__ part,
                          float* __restrict__ suf) {
    int col = blockIdx.y * 256 + threadIdx.x;
    int seg = blockIdx.x;
    float run = 0.f;
    for (int s2 = seg + 1; s2 < 16; s2++) run += part[s2 * 1024 + col];
    for (int t = seg * 128 + 127; t >= seg * 128; t--) {
        suf[(size_t)t * 1024 + col] = run;
        run += qkv[(size_t)t * 3072 + 2048 + col];
    }
}

// ---------------- attn = scale*(Q@M) - 1e9*suf, emit hi/lo split ----------------
__global__ __launch_bounds__(256)
void attn_combine(const float* __restrict__ qkv, const float* __restrict__ mp,
                  const float* __restrict__ suf,
                  __nv_bfloat16* __restrict__ ahi, __nv_bfloat16* __restrict__ alo) {
    const int head = blockIdx.y;
    const int s0 = blockIdx.x * 64;
    __shared__ float Qs[64][65];
    __shared__ float Ms[64][65];
    const int tid = threadIdx.x;
    for (int i = tid; i < 4096; i += 256) {
        int r = i >> 6, c = i & 63;
        Qs[r][c] = qkv[(size_t)(s0 + r) * 3072 + head * DH + c];
        float mv = 0.f;
        #pragma unroll
        for (int sg = 0; sg < 16; sg++) mv += mp[(size_t)(sg * 16 + head) * 4096 + i];
        Ms[r][c] = mv;
    }
    __syncthreads();
    const int tr = tid >> 4, tc = tid & 15;
    float acc[4][4] = {};
    #pragma unroll 4
    for (int hp = 0; hp < 64; hp++) {
        float a[4], b[4];
        #pragma unroll
        for (int i = 0; i < 4; i++) a[i] = Qs[tr * 4 + i][hp];
        #pragma unroll
        for (int j = 0; j < 4; j++) b[j] = Ms[hp][tc * 4 + j];
        #pragma unroll
        for (int i = 0; i < 4; i++)
            #pragma unroll
            for (int j = 0; j < 4; j++)
                acc[i][j] = fmaf(a[i], b[j], acc[i][j]);
    }
    #pragma unroll
    for (int i = 0; i < 4; i++) {
        int s = s0 + tr * 4 + i;
        size_t sb = (size_t)s * 1024 + head * DH + tc * 4;
        float o[4];
        #pragma unroll
        for (int j = 0; j < 4; j++)
            o[j] = 0.125f * acc[i][j] - 1e9f * suf[sb + j];
        uint2 hv, lv;
        split4(o[0], o[1], o[2], o[3], hv, lv);
        *(uint2*)(ahi + sb) = hv;
        *(uint2*)(alo + sb) = lv;
    }
}

// ---------------- LayerNorm (+residual) + fused split, warp-shuffle reduce ----------------
template<bool ADD, bool WF32, int OUTK>
__global__ __launch_bounds__(256)
void ln_kernel(const float* __restrict__ t, const float* __restrict__ xin,
               const float* __restrict__ g, const float* __restrict__ b,
               float* __restrict__ outf,
               __nv_bfloat16* __restrict__ hi, __nv_bfloat16* __restrict__ lo,
               __half* __restrict__ outh) {
    const int row = blockIdx.x;
    const int tid = threadIdx.x;
    const int wid = tid >> 5, lane = tid & 31;
    float4 v = *(const float4*)(t + (size_t)row * H + tid * 4);
    __shared__ float wred[8];
    __shared__ float stat[2];

    float s = v.x + v.y + v.z + v.w;
    #pragma unroll
    for (int o = 16; o > 0; o >>= 1) s += __shfl_xor_sync(0xFFFFFFFFu, s, o);
    if (lane == 0) wred[wid] = s;
    __syncthreads();
    if (tid == 0) {
        float tot = 0.f;
        #pragma unroll
        for (int w = 0; w < 8; w++) tot += wred[w];
        stat[0] = tot * (1.0f / H);
    }
    __syncthreads();
    float mean = stat[0];

    float dx = v.x - mean, dy = v.y - mean, dz = v.z - mean, dw = v.w - mean;
    float vs = dx * dx + dy * dy + dz * dz + dw * dw;
    #pragma unroll
    for (int o = 16; o > 0; o >>= 1) vs += __shfl_xor_sync(0xFFFFFFFFu, vs, o);
    if (lane == 0) wred[wid] = vs;
    __syncthreads();
    if (tid == 0) {
        float tot = 0.f;
        #pragma unroll
        for (int w = 0; w < 8; w++) tot += wred[w];
        stat[1] = rsqrtf(tot * (1.0f / H) + 1e-5f);
    }
    __syncthreads();
    float rstd = stat[1];

    int h = tid * 4;
    float4 gv = *(const float4*)(g + h);
    float4 bv = *(const float4*)(b + h);
    float o0 = dx * rstd * gv.x + bv.x;
    float o1 = dy * rstd * gv.y + bv.y;
    float o2 = dz * rstd * gv.z + bv.z;
    float o3 = dw * rstd * gv.w + bv.w;
    if (ADD) {
        float4 xv = *(const float4*)(xin + (size_t)row * H + h);
        o0 += xv.x; o1 += xv.y; o2 += xv.z; o3 += xv.w;
    }
    if (WF32) *(float4*)(outf + (size_t)row * H + h) = make_float4(o0, o1, o2, o3);
    if (OUTK == 0) {
        uint2 hv, lv;
        split4(o0, o1, o2, o3, hv, lv);
        *(uint2*)(hi + (size_t)row * H + h) = hv;
        *(uint2*)(lo + (size_t)row * H + h) = lv;
    } else {
        __half2 h0 = __floats2half2_rn(o0, o1);
        __half2 h1 = __floats2half2_rn(o2, o3);
        *(uint2*)(outh + (size_t)row * H + h) = make_uint2(*(uint32_t*)&h0, *(uint32_t*)&h1);
    }
}

// ---------------- launch ----------------
extern "C" void kernel_launch(void* const* d_in, const int* in_sizes, int n_in,
                              void* d_out, int out_size) {
    const int*   tokens = (const int*)  d_in[0];
    const float* emb    = (const float*)d_in[1];
    const float* pos    = (const float*)d_in[2];
    const float* Wq     = (const float*)d_in[3];
    const float* Wk     = (const float*)d_in[4];
    const float* Wv     = (const float*)d_in[5];
    const float* Wp     = (const float*)d_in[6];
    const float* bp     = (const float*)d_in[7];
    const float* W1     = (const float*)d_in[8];
    const float* b1     = (const float*)d_in[9];
    const float* W2     = (const float*)d_in[10];
    const float* b2     = (const float*)d_in[11];
    const float* ln_g   = (const float*)d_in[12];
    const float* ln_b   = (const float*)d_in[13];
    const float* Wlm    = (const float*)d_in[14];
    const float* blm    = (const float*)d_in[15];
    float* out = (float*)d_out;
    const int Vv = in_sizes[15];

    float *x, *tmp, *res, *qkv, *suf, *m, *part, *zb;
    __nv_bfloat16 *ahi, *alo, *bhi, *blo;
    __nv_bfloat16 *btqkv_hi, *btqkv_lo, *btp_hi, *btp_lo;
    __nv_bfloat16 *bt1_hi, *bt1_lo, *bt2_hi, *bt2_lo;
    __half *wlm, *xf16;
    cudaGetSymbolAddress((void**)&x, g_x);       cudaGetSymbolAddress((void**)&tmp, g_tmp);
    cudaGetSymbolAddress((void**)&res, g_res);   cudaGetSymbolAddress((void**)&qkv, g_qkv);
    cudaGetSymbolAddress((void**)&suf, g_suf);   cudaGetSymbolAddress((void**)&m, g_m);
    cudaGetSymbolAddress((void**)&part, g_part); cudaGetSymbolAddress((void**)&zb, g_zb);
    cudaGetSymbolAddress((void**)&ahi, g_ahi);   cudaGetSymbolAddress((void**)&alo, g_alo);
    cudaGetSymbolAddress((void**)&bhi, g_bhi);   cudaGetSymbolAddress((void**)&blo, g_blo);
    cudaGetSymbolAddress((void**)&btqkv_hi, g_btqkv_hi);
    cudaGetSymbolAddress((void**)&btqkv_lo, g_btqkv_lo);
    cudaGetSymbolAddress((void**)&btp_hi, g_btp_hi); cudaGetSymbolAddress((void**)&btp_lo, g_btp_lo);
    cudaGetSymbolAddress((void**)&bt1_hi, g_bt1_hi); cudaGetSymbolAddress((void**)&bt1_lo, g_bt1_lo);
    cudaGetSymbolAddress((void**)&bt2_hi, g_bt2_hi); cudaGetSymbolAddress((void**)&bt2_lo, g_bt2_lo);
    cudaGetSymbolAddress((void**)&wlm, g_wlm_f16);   cudaGetSymbolAddress((void**)&xf16, g_xf_f16);

    cudaFuncSetAttribute(gemm_hmma64<0>, cudaFuncAttributeMaxDynamicSharedMemorySize, GEMM64_SMEM);
    cudaFuncSetAttribute(gemm_hmma64<1>, cudaFuncAttributeMaxDynamicSharedMemorySize, GEMM64_SMEM);
    cudaFuncSetAttribute(gemm_f16, cudaFuncAttributeMaxDynamicSharedMemorySize, F16_SMEM);

    dim3 tb(256);
    // idx0: embed
    embed_kernel<<<(S * H) / 1024, 256>>>(tokens, emb, pos, x, ahi, alo);
    // idx1: combined qkv weight transpose (rows 0..1023=Q, 1024..2047=K, 2048..3071=V)
    transpose_split<1><<<dim3(2, 8, 3 * NLAYERS * NH), tb>>>(Wq, Wk, Wv,
                                                             btqkv_hi, btqkv_lo, H, DH);
    // idx2: proj weights
    transpose_split<0><<<dim3(32, 8, NLAYERS), tb>>>(Wp, nullptr, nullptr,
                                                     btp_hi, btp_lo, H, H);
    // idx3: QKV GEMM layer 0 (Q/K columns single-pass, V columns bf16x3)
    gemm_hmma64<0><<<dim3(24, 32), 256, GEMM64_SMEM>>>(ahi, alo, btqkv_hi, btqkv_lo,
                                                       zb, qkv, nullptr, nullptr, 3072, H, 2048);
    // remaining weight transposes
    transpose_split<0><<<dim3(128, 8, NLAYERS), tb>>>(W1, nullptr, nullptr, bt1_hi, bt1_lo, H, FF);
    transpose_split<0><<<dim3(32, 32, NLAYERS), tb>>>(W2, nullptr, nullptr, bt2_hi, bt2_lo, FF, H);
    transpose_f16<<<dim3((Vv + 31) / 32, 8), tb>>>(Wlm, wlm, H, Vv);

    for (int l = 0; l < NLAYERS; l++) {
        size_t oQ = (size_t)l * 3072 * H;
        size_t oH = (size_t)l * H * H;
        size_t oF = (size_t)l * H * FF;

        if (l > 0)
            gemm_hmma64<0><<<dim3(24, 32), 256, GEMM64_SMEM>>>(ahi, alo, btqkv_hi + oQ, btqkv_lo + oQ,
                                                               zb, qkv, nullptr, nullptr, 3072, H, 2048);
        ktv_kernel<<<256, 256>>>(qkv, m, part);
        suf_apply<<<dim3(16, 4), 256>>>(qkv, part, suf);
        attn_combine<<<dim3(S / 64, NH), 256>>>(qkv, m, suf, ahi, alo);

        gemm_hmma64<0><<<dim3(8, 32), 256, GEMM64_SMEM>>>(ahi, alo, btp_hi + oH, btp_lo + oH,
                                                          bp + (size_t)l * H, tmp, nullptr, nullptr,
                                                          H, H, 0);
        ln_kernel<true, true, 0><<<S, 256>>>(tmp, x, ln_g, ln_b, res, ahi, alo, nullptr);

        gemm_hmma64<1><<<dim3(32, 32), 256, GEMM64_SMEM>>>(ahi, alo, bt1_hi + oF, bt1_lo + oF,
                                                           b1 + (size_t)l * FF, nullptr, bhi, blo,
                                                           FF, H, 0);
        gemm_hmma64<0><<<dim3(8, 32), 256, GEMM64_SMEM>>>(bhi, blo, bt2_hi + oF, bt2_lo + oF,
                                                          b2 + (size_t)l * H, tmp, nullptr, nullptr,
                                                          H, FF, 0);
        ln_kernel<true, true, 0><<<S, 256>>>(tmp, res, ln_g, ln_b, x, ahi, alo, nullptr);
    }

    // final LN -> fp16, LM head in fp16 HMMA
    ln_kernel<false, false, 1><<<S, 256>>>(x, nullptr, ln_g, ln_b, nullptr, nullptr, nullptr, xf16);
    gemm_f16<<<dim3(16, VPAD / 128), 256, F16_SMEM>>>(xf16, wlm, blm, out, Vv, H);
}

// round 13
// speedup vs baseline: 1.5480x; 1.0269x over previous
#include <cuda_runtime.h>
#include <cuda_bf16.h>
#include <cuda_fp16.h>
#include <math.h>
#include <stdint.h>

#define S  2048
#define H  1024
#define NH 16
#define DH 64
#define FF 4096
#define NLAYERS 6
#define VPAD 50432     // 50257 padded to multiple of 128

#define SZ_SH (S*H)

// ---------------- device scratch ----------------
__device__ __align__(16) float g_x[SZ_SH];
__device__ __align__(16) float g_tmp[SZ_SH];
__device__ __align__(16) float g_res[SZ_SH];
__device__ __align__(16) float g_qkv[S*3072];
__device__ __align__(16) float g_m[16*NH*DH*DH];    // split-K partials (16 segs)
__device__ __align__(16) float g_part[32*1024];     // V column sums per 64-row block
__device__ __align__(16) float g_zb[8192];          // zero bias (never written)

// activation hi/lo
__device__ __align__(128) __nv_bfloat16 g_ahi[S*FF];
__device__ __align__(128) __nv_bfloat16 g_alo[S*FF];
__device__ __align__(128) __nv_bfloat16 g_bhi[S*FF];
__device__ __align__(128) __nv_bfloat16 g_blo[S*FF];

// weight hi/lo, K-major transposed [N,K]
__device__ __align__(128) __nv_bfloat16 g_btqkv_hi[NLAYERS*3072*H];
__device__ __align__(128) __nv_bfloat16 g_btqkv_lo[NLAYERS*3072*H];
__device__ __align__(128) __nv_bfloat16 g_btp_hi[NLAYERS*H*H];
__device__ __align__(128) __nv_bfloat16 g_btp_lo[NLAYERS*H*H];
__device__ __align__(128) __nv_bfloat16 g_bt1_hi[NLAYERS*H*FF];
__device__ __align__(128) __nv_bfloat16 g_bt1_lo[NLAYERS*H*FF];
__device__ __align__(128) __nv_bfloat16 g_bt2_hi[NLAYERS*H*FF];
__device__ __align__(128) __nv_bfloat16 g_bt2_lo[NLAYERS*H*FF];
__device__ __align__(128) __half g_wlm_f16[VPAD*H];  // fp16 LM weights, pad rows stay zero
__device__ __align__(128) __half g_xf_f16[SZ_SH];    // fp16 final-LN activations

// ---------------- PTX helpers ----------------
__device__ __forceinline__ uint32_t smem_u32(const void* p) {
    uint32_t a;
    asm("{ .reg .u64 t; cvta.to.shared.u64 t, %1; cvt.u32.u64 %0, t; }" : "=r"(a) : "l"(p));
    return a;
}
__device__ __forceinline__ void cp16(uint32_t dst, const void* src) {
    asm volatile("cp.async.cg.shared.global [%0], [%1], 16;" :: "r"(dst), "l"(src));
}
__device__ __forceinline__ void cp_commit() { asm volatile("cp.async.commit_group;" ::: "memory"); }
template<int N> __device__ __forceinline__ void cp_wait() {
    asm volatile("cp.async.wait_group %0;" :: "n"(N) : "memory");
}
__device__ __forceinline__ void ldsm4(uint32_t& r0, uint32_t& r1, uint32_t& r2, uint32_t& r3,
                                      uint32_t addr) {
    asm volatile("ldmatrix.sync.aligned.m8n8.x4.shared.b16 {%0,%1,%2,%3}, [%4];"
                 : "=r"(r0), "=r"(r1), "=r"(r2), "=r"(r3) : "r"(addr));
}
__device__ __forceinline__ void mma16816(float& d0, float& d1, float& d2, float& d3,
                                         uint32_t a0, uint32_t a1, uint32_t a2, uint32_t a3,
                                         uint32_t b0, uint32_t b1) {
    asm volatile("mma.sync.aligned.m16n8k16.row.col.f32.bf16.bf16.f32 "
                 "{%0,%1,%2,%3}, {%4,%5,%6,%7}, {%8,%9}, {%0,%1,%2,%3};"
                 : "+f"(d0), "+f"(d1), "+f"(d2), "+f"(d3)
                 : "r"(a0), "r"(a1), "r"(a2), "r"(a3), "r"(b0), "r"(b1));
}
__device__ __forceinline__ void mma16816h(float& d0, float& d1, float& d2, float& d3,
                                          uint32_t a0, uint32_t a1, uint32_t a2, uint32_t a3,
                                          uint32_t b0, uint32_t b1) {
    asm volatile("mma.sync.aligned.m16n8k16.row.col.f32.f16.f16.f32 "
                 "{%0,%1,%2,%3}, {%4,%5,%6,%7}, {%8,%9}, {%0,%1,%2,%3};"
                 : "+f"(d0), "+f"(d1), "+f"(d2), "+f"(d3)
                 : "r"(a0), "r"(a1), "r"(a2), "r"(a3), "r"(b0), "r"(b1));
}

__device__ __forceinline__ float gelu_exact(float x) {
    return 0.5f * x * (1.0f + erff(x * 0.70710678118654752f));
}

// swizzled 64B-row offset: row r, 16B chunk c (0..3)
__device__ __forceinline__ uint32_t swz(uint32_t r, uint32_t c) {
    return r * 64 + ((c ^ ((r >> 1) & 3)) << 4);
}

// pack 4 floats into bf16 hi/lo pairs (8B each)
__device__ __forceinline__ void split4(float o0, float o1, float o2, float o3,
                                       uint2& hv, uint2& lv) {
    __nv_bfloat162 h01 = __floats2bfloat162_rn(o0, o1);
    __nv_bfloat162 h23 = __floats2bfloat162_rn(o2, o3);
    float e0 = o0 - __bfloat162float(h01.x), e1 = o1 - __bfloat162float(h01.y);
    float e2 = o2 - __bfloat162float(h23.x), e3 = o3 - __bfloat162float(h23.y);
    __nv_bfloat162 l01 = __floats2bfloat162_rn(e0, e1);
    __nv_bfloat162 l23 = __floats2bfloat162_rn(e2, e3);
    hv = make_uint2(*(uint32_t*)&h01, *(uint32_t*)&h23);
    lv = make_uint2(*(uint32_t*)&l01, *(uint32_t*)&l23);
}

// ---------------- TM64 HMMA GEMM (bf16x3): CTA 64x128, BK=32, 4-stage ----------------
// 8 warps (2x4) of 32x32 tiles. MODE 0: fp32 + bias. MODE 1: gelu + bf16 hi/lo.
// n1pass: CTAs whose columns lie below this bound use single-pass bf16 (hi only),
// processing TWO K-chunks per stage (same 24KB stage footprint, half the barriers).
#define S64_AHI 0
#define S64_ALO 4096
#define S64_BHI 8192
#define S64_BLO 16384
#define STAGE64 24576
#define GEMM64_SMEM (4*STAGE64)
// lite double-chunk layout within a stage: A0@0, A1@4096, B0@8192, B1@16384

template<int MODE>
__global__ __launch_bounds__(256, 2)
void gemm_hmma64(const __nv_bfloat16* __restrict__ Ahi, const __nv_bfloat16* __restrict__ Alo,
                 const __nv_bfloat16* __restrict__ Bhi, const __nv_bfloat16* __restrict__ Blo,
                 const float* __restrict__ bias, float* __restrict__ C,
                 __nv_bfloat16* __restrict__ Chi, __nv_bfloat16* __restrict__ Clo,
                 int N, int K, int n1pass) {
    extern __shared__ char smem[];
    const uint32_t sb = smem_u32(smem);
    const int tid  = threadIdx.x;
    const int wid  = tid >> 5;
    const int lane = tid & 31;
    const int wrow = wid & 1;
    const int wcol = wid >> 1;
    const int bm = blockIdx.y << 6;
    const long bn = (long)blockIdx.x << 7;
    const bool lite = (bn + 128 <= n1pass);

    const uint32_t rt = tid >> 2, ct = tid & 3;
    const uint32_t soA  = swz(rt, ct);
    const uint32_t soB1 = swz(rt + 64, ct);

    #define LOAD_FULL(kc, s) do {                                                      \
        uint32_t st_ = sb + (s) * STAGE64;                                              \
        size_t ga  = ((size_t)(bm + rt) * K + (kc) * 32 + ct * 8) * 2;                  \
        size_t gb0 = ((size_t)(bn + rt) * K + (kc) * 32 + ct * 8) * 2;                  \
        size_t gb1 = ((size_t)(bn + rt + 64) * K + (kc) * 32 + ct * 8) * 2;             \
        cp16(st_ + S64_AHI + soA,  (const char*)Ahi + ga);                              \
        cp16(st_ + S64_ALO + soA,  (const char*)Alo + ga);                              \
        cp16(st_ + S64_BHI + soA,  (const char*)Bhi + gb0);                             \
        cp16(st_ + S64_BLO + soA,  (const char*)Blo + gb0);                             \
        cp16(st_ + S64_BHI + soB1, (const char*)Bhi + gb1);                             \
        cp16(st_ + S64_BLO + soB1, (const char*)Blo + gb1);                             \
    } while (0)

    // lite: two k-chunks (2*kc2, 2*kc2+1) per stage, hi operands only
    #define LOAD_LITE2(kc2, s) do {                                                    \
        uint32_t st_ = sb + (s) * STAGE64;                                              \
        size_t ga0 = ((size_t)(bm + rt) * K + (kc2) * 64 + ct * 8) * 2;                 \
        size_t gb0 = ((size_t)(bn + rt) * K + (kc2) * 64 + ct * 8) * 2;                 \
        size_t gb1 = ((size_t)(bn + rt + 64) * K + (kc2) * 64 + ct * 8) * 2;            \
        cp16(st_ + 0     + soA,  (const char*)Ahi + ga0);                               \
        cp16(st_ + 4096  + soA,  (const char*)Ahi + ga0 + 64);                          \
        cp16(st_ + 8192  + soA,  (const char*)Bhi + gb0);                               \
        cp16(st_ + 8192  + soB1, (const char*)Bhi + gb1);                               \
        cp16(st_ + 16384 + soA,  (const char*)Bhi + gb0 + 64);                          \
        cp16(st_ + 16384 + soB1, (const char*)Bhi + gb1 + 64);                          \
    } while (0)

    const int lane8 = lane & 7, sub = lane >> 3;
    const uint32_t ra = wrow * 32 + (sub & 1) * 8 + lane8;
    const uint32_t aks0 = swz(ra, (sub >> 1));
    const uint32_t aks1 = swz(ra, (sub >> 1) + 2);
    const uint32_t rb = wcol * 32 + lane8;
    const uint32_t boffs = swz(rb, sub);

    float acc[2][4][4];
    #pragma unroll
    for (int i = 0; i < 2; i++)
        #pragma unroll
        for (int j = 0; j < 4; j++)
            #pragma unroll
            for (int e = 0; e < 4; e++) acc[i][j][e] = 0.f;

    int slot = 0;
    if (!lite) {
        const int nc = K >> 5;
        LOAD_FULL(0, 0); cp_commit();
        LOAD_FULL(1, 1); cp_commit();
        LOAD_FULL(2, 2); cp_commit();
        for (int it = 0; it < nc; it++) {
            cp_wait<2>();
            __syncthreads();
            if (it + 3 < nc) {
                int ns = slot + 3; if (ns >= 4) ns -= 4;
                LOAD_FULL(it + 3, ns);
            }
            cp_commit();
            const uint32_t st = sb + slot * STAGE64;

            uint32_t bh[4][4], bl[4][4], ah[2][2][4], al[2][2][4];
            #pragma unroll
            for (int nj = 0; nj < 4; nj++) {
                ldsm4(bh[nj][0], bh[nj][1], bh[nj][2], bh[nj][3], st + S64_BHI + boffs + nj * 512);
                ldsm4(bl[nj][0], bl[nj][1], bl[nj][2], bl[nj][3], st + S64_BLO + boffs + nj * 512);
            }
            #pragma unroll
            for (int mi = 0; mi < 2; mi++) {
                ldsm4(ah[0][mi][0], ah[0][mi][1], ah[0][mi][2], ah[0][mi][3],
                      st + S64_AHI + aks0 + mi * 1024);
                ldsm4(ah[1][mi][0], ah[1][mi][1], ah[1][mi][2], ah[1][mi][3],
                      st + S64_AHI + aks1 + mi * 1024);
                ldsm4(al[0][mi][0], al[0][mi][1], al[0][mi][2], al[0][mi][3],
                      st + S64_ALO + aks0 + mi * 1024);
                ldsm4(al[1][mi][0], al[1][mi][1], al[1][mi][2], al[1][mi][3],
                      st + S64_ALO + aks1 + mi * 1024);
            }
            #pragma unroll
            for (int ks = 0; ks < 2; ks++) {
                #pragma unroll
                for (int mi = 0; mi < 2; mi++)
                    #pragma unroll
                    for (int nj = 0; nj < 4; nj++)
                        mma16816(acc[mi][nj][0], acc[mi][nj][1], acc[mi][nj][2], acc[mi][nj][3],
                                 ah[ks][mi][0], ah[ks][mi][1], ah[ks][mi][2], ah[ks][mi][3],
                                 bh[nj][ks * 2], bh[nj][ks * 2 + 1]);
                #pragma unroll
                for (int mi = 0; mi < 2; mi++)
                    #pragma unroll
                    for (int nj = 0; nj < 4; nj++)
                        mma16816(acc[mi][nj][0], acc[mi][nj][1], acc[mi][nj][2], acc[mi][nj][3],
                                 ah[ks][mi][0], ah[ks][mi][1], ah[ks][mi][2], ah[ks][mi][3],
                                 bl[nj][ks * 2], bl[nj][ks * 2 + 1]);
                #pragma unroll
                for (int mi = 0; mi < 2; mi++)
                    #pragma unroll
                    for (int nj = 0; nj < 4; nj++)
                        mma16816(acc[mi][nj][0], acc[mi][nj][1], acc[mi][nj][2], acc[mi][nj][3],
                                 al[ks][mi][0], al[ks][mi][1], al[ks][mi][2], al[ks][mi][3],
                                 bh[nj][ks * 2], bh[nj][ks * 2 + 1]);
            }
            if (++slot == 4) slot = 0;
        }
    } else {
        const int nc2 = K >> 6;
        LOAD_LITE2(0, 0); cp_commit();
        LOAD_LITE2(1, 1); cp_commit();
        LOAD_LITE2(2, 2); cp_commit();
        for (int it = 0; it < nc2; it++) {
            cp_wait<2>();
            __syncthreads();
            if (it + 3 < nc2) {
                int ns = slot + 3; if (ns >= 4) ns -= 4;
                LOAD_LITE2(it + 3, ns);
            }
            cp_commit();
            const uint32_t st = sb + slot * STAGE64;

            #pragma unroll
            for (int ch = 0; ch < 2; ch++) {
                uint32_t bh[4][4], ah[2][2][4];
                #pragma unroll
                for (int nj = 0; nj < 4; nj++)
                    ldsm4(bh[nj][0], bh[nj][1], bh[nj][2], bh[nj][3],
                          st + 8192 + ch * 8192 + boffs + nj * 512);
                #pragma unroll
                for (int mi = 0; mi < 2; mi++) {
                    ldsm4(ah[0][mi][0], ah[0][mi][1], ah[0][mi][2], ah[0][mi][3],
                          st + ch * 4096 + aks0 + mi * 1024);
                    ldsm4(ah[1][mi][0], ah[1][mi][1], ah[1][mi][2], ah[1][mi][3],
                          st + ch * 4096 + aks1 + mi * 1024);
                }
                #pragma unroll
                for (int ks = 0; ks < 2; ks++)
                    #pragma unroll
                    for (int mi = 0; mi < 2; mi++)
                        #pragma unroll
                        for (int nj = 0; nj < 4; nj++)
                            mma16816(acc[mi][nj][0], acc[mi][nj][1], acc[mi][nj][2], acc[mi][nj][3],
                                     ah[ks][mi][0], ah[ks][mi][1], ah[ks][mi][2], ah[ks][mi][3],
                                     bh[nj][ks * 2], bh[nj][ks * 2 + 1]);
            }
            if (++slot == 4) slot = 0;
        }
    }

    const int gr = lane >> 2;
    const int gc = (lane & 3) * 2;
    #pragma unroll
    for (int mi = 0; mi < 2; mi++) {
        size_t row0 = (size_t)(bm + wrow * 32 + mi * 16 + gr) * N;
        size_t row1 = row0 + (size_t)8 * N;
        #pragma unroll
        for (int nj = 0; nj < 4; nj++) {
            long c = bn + wcol * 32 + nj * 8 + gc;
            float b0 = bias[c], b1 = bias[c + 1];
            if (MODE == 0) {
                C[row0 + c]     = acc[mi][nj][0] + b0;
                C[row0 + c + 1] = acc[mi][nj][1] + b1;
                C[row1 + c]     = acc[mi][nj][2] + b0;
                C[row1 + c + 1] = acc[mi][nj][3] + b1;
            } else {
                float v0 = gelu_exact(acc[mi][nj][0] + b0);
                float v1 = gelu_exact(acc[mi][nj][1] + b1);
                float v2 = gelu_exact(acc[mi][nj][2] + b0);
                float v3 = gelu_exact(acc[mi][nj][3] + b1);
                __nv_bfloat162 hp0 = __floats2bfloat162_rn(v0, v1);
                __nv_bfloat162 hp1 = __floats2bfloat162_rn(v2, v3);
                float e0 = v0 - __bfloat162float(hp0.x), e1 = v1 - __bfloat162float(hp0.y);
                float e2 = v2 - __bfloat162float(hp1.x), e3 = v3 - __bfloat162float(hp1.y);
                __nv_bfloat162 lp0 = __floats2bfloat162_rn(e0, e1);
                __nv_bfloat162 lp1 = __floats2bfloat162_rn(e2, e3);
                *(uint32_t*)(Chi + row0 + c) = *(uint32_t*)&hp0;
                *(uint32_t*)(Clo + row0 + c) = *(uint32_t*)&lp0;
                *(uint32_t*)(Chi + row1 + c) = *(uint32_t*)&hp1;
                *(uint32_t*)(Clo + row1 + c) = *(uint32_t*)&lp1;
            }
        }
    }
    #undef LOAD_FULL
    #undef LOAD_LITE2
}

// ---------------- fp16 single-term GEMM (LM head), 4-stage ----------------
#define F_TA 0
#define F_TB 8192
#define F_STAGE 16384
#define F16_SMEM (4*F_STAGE)

__global__ __launch_bounds__(256, 2)
void gemm_f16(const __half* __restrict__ A, const __half* __restrict__ B,
              const float* __restrict__ bias, float* __restrict__ C, int N, int K) {
    extern __shared__ char smem[];
    const uint32_t sb = smem_u32(smem);
    const int tid  = threadIdx.x;
    const int wid  = tid >> 5;
    const int lane = tid & 31;
    const int wrow = wid & 1;
    const int wcol = wid >> 1;
    const int bm = blockIdx.x << 7;
    const long bn = (long)blockIdx.y << 7;
    const int nc = K >> 5;

    const uint32_t r0t = tid >> 2, c0t = tid & 3;
    const uint32_t r1t = r0t + 64;
    const uint32_t so0 = swz(r0t, c0t);
    const uint32_t so1 = swz(r1t, c0t);

    #define LOAD_STAGE_F(kc, s) do {                                                   \
        uint32_t st_ = sb + (s) * F_STAGE;                                              \
        {                                                                               \
            size_t ga = ((size_t)(bm + r0t) * K + (kc) * 32 + c0t * 8) * 2;             \
            size_t gb = ((size_t)(bn + r0t) * K + (kc) * 32 + c0t * 8) * 2;             \
            cp16(st_ + F_TA + so0, (const char*)A + ga);                                \
            cp16(st_ + F_TB + so0, (const char*)B + gb);                                \
        }                                                                               \
        {                                                                               \
            size_t ga = ((size_t)(bm + r1t) * K + (kc) * 32 + c0t * 8) * 2;             \
            size_t gb = ((size_t)(bn + r1t) * K + (kc) * 32 + c0t * 8) * 2;             \
            cp16(st_ + F_TA + so1, (const char*)A + ga);                                \
            cp16(st_ + F_TB + so1, (const char*)B + gb);                                \
        }                                                                               \
    } while (0)

    LOAD_STAGE_F(0, 0); cp_commit();
    LOAD_STAGE_F(1, 1); cp_commit();
    LOAD_STAGE_F(2, 2); cp_commit();

    const int lane8 = lane & 7, sub = lane >> 3;
    const uint32_t ra = wrow * 64 + (sub & 1) * 8 + lane8;
    const uint32_t aks0 = swz(ra, (sub >> 1));
    const uint32_t aks1 = swz(ra, (sub >> 1) + 2);
    const uint32_t rb = wcol * 32 + lane8;
    const uint32_t boffs = swz(rb, sub);

    float acc[4][4][4];
    #pragma unroll
    for (int i = 0; i < 4; i++)
        #pragma unroll
        for (int j = 0; j < 4; j++)
            #pragma unroll
            for (int e = 0; e < 4; e++) acc[i][j][e] = 0.f;

    int slot = 0;
    for (int it = 0; it < nc; it++) {
        cp_wait<2>();
        __syncthreads();
        if (it + 3 < nc) {
            int ns = slot + 3; if (ns >= 4) ns -= 4;
            LOAD_STAGE_F(it + 3, ns);
        }
        cp_commit();
        const uint32_t st = sb + slot * F_STAGE;

        uint32_t bf[4][4];
        #pragma unroll
        for (int nj = 0; nj < 4; nj++)
            ldsm4(bf[nj][0], bf[nj][1], bf[nj][2], bf[nj][3], st + F_TB + boffs + nj * 512);
        #pragma unroll
        for (int ks = 0; ks < 2; ks++) {
            const uint32_t ao = (ks == 0) ? aks0 : aks1;
            uint32_t a[4][4];
            #pragma unroll
            for (int mi = 0; mi < 4; mi++)
                ldsm4(a[mi][0], a[mi][1], a[mi][2], a[mi][3], st + F_TA + ao + mi * 1024);
            #pragma unroll
            for (int mi = 0; mi < 4; mi++)
                #pragma unroll
                for (int nj = 0; nj < 4; nj++)
                    mma16816h(acc[mi][nj][0], acc[mi][nj][1], acc[mi][nj][2], acc[mi][nj][3],
                              a[mi][0], a[mi][1], a[mi][2], a[mi][3],
                              bf[nj][ks * 2], bf[nj][ks * 2 + 1]);
        }
        if (++slot == 4) slot = 0;
    }

    const int gr = lane >> 2;
    const int gc = (lane & 3) * 2;
    #pragma unroll
    for (int mi = 0; mi < 4; mi++) {
        size_t row0 = (size_t)(bm + wrow * 64 + mi * 16 + gr) * N;
        size_t row1 = row0 + (size_t)8 * N;
        #pragma unroll
        for (int nj = 0; nj < 4; nj++) {
            long c = bn + wcol * 32 + nj * 8 + gc;
            if (c < N) {
                C[row0 + c] = acc[mi][nj][0] + bias[c];
                C[row1 + c] = acc[mi][nj][2] + bias[c];
            }
            if (c + 1 < N) {
                C[row0 + c + 1] = acc[mi][nj][1] + bias[c + 1];
                C[row1 + c + 1] = acc[mi][nj][3] + bias[c + 1];
            }
        }
    }
    #undef LOAD_STAGE_F
}

// ---------------- weight transpose + split (bf16 hi/lo), 16B stores ----------------
template<int QKV>
__global__ __launch_bounds__(256)
void transpose_split(const float* __restrict__ src0, const float* __restrict__ src1,
                     const float* __restrict__ src2,
                     __nv_bfloat16* __restrict__ hi, __nv_bfloat16* __restrict__ lo,
                     int R, int C) {
    __shared__ float t[128][33];
    int z = blockIdx.z;
    const float* src = src0;
    int sel = 0;
    if (QKV) {
        sel = z / (NLAYERS * NH);
        z   = z % (NLAYERS * NH);
        src = (sel == 0) ? src0 : (sel == 1) ? src1 : src2;
    }
    const size_t ib = (size_t)z * R * C;
    size_t ob;
    if (QKV) ob = (size_t)(z >> 4) * (3072 * 1024) + (size_t)sel * (1024 * 1024)
                + (size_t)(z & 15) * (64 * 1024);
    else     ob = ib;
    const int r0 = blockIdx.y * 128, c0 = blockIdx.x * 32;
    const int cc = threadIdx.x & 31, rb = threadIdx.x >> 5;
    const bool cok = (c0 + cc) < C;
    #pragma unroll
    for (int p = 0; p < 16; p++) {
        int rr = rb + p * 8;
        t[rr][cc] = cok ? src[ib + (size_t)(r0 + rr) * C + c0 + cc] : 0.f;
    }
    __syncthreads();
    const int oc2 = threadIdx.x >> 4;
    const int r8  = (threadIdx.x & 15) * 8;
    const bool wlo = (!QKV) || (sel == 2);
    #pragma unroll
    for (int cp = 0; cp < 2; cp++) {
        int col = cp * 16 + oc2;
        if (c0 + col < C) {
            uint32_t hw[4], lw[4];
            #pragma unroll
            for (int i = 0; i < 4; i++) {
                float f0 = t[r8 + 2 * i][col], f1 = t[r8 + 2 * i + 1][col];
                __nv_bfloat162 hp = __floats2bfloat162_rn(f0, f1);
                hw[i] = *(uint32_t*)&hp;
                float e0 = f0 - __bfloat162float(hp.x);
                float e1 = f1 - __bfloat162float(hp.y);
                __nv_bfloat162 lp = __floats2bfloat162_rn(e0, e1);
                lw[i] = *(uint32_t*)&lp;
            }
            size_t obase = ob + (size_t)(c0 + col) * R + r0 + r8;
            *(uint4*)(hi + obase) = make_uint4(hw[0], hw[1], hw[2], hw[3]);
            if (wlo) *(uint4*)(lo + obase) = make_uint4(lw[0], lw[1], lw[2], lw[3]);
        }
    }
}

// ---------------- fp16 weight transpose (LM head), 16B stores ----------------
__global__ __launch_bounds__(256)
void transpose_f16(const float* __restrict__ src, __half* __restrict__ out, int R, int C) {
    __shared__ float t[128][33];
    const int r0 = blockIdx.y * 128, c0 = blockIdx.x * 32;
    const int cc = threadIdx.x & 31, rb = threadIdx.x >> 5;
    const bool cok = (c0 + cc) < C;
    #pragma unroll
    for (int p = 0; p < 16; p++) {
        int rr = rb + p * 8;
        t[rr][cc] = cok ? src[(size_t)(r0 + rr) * C + c0 + cc] : 0.f;
    }
    __syncthreads();
    const int oc2 = threadIdx.x >> 4;
    const int r8  = (threadIdx.x & 15) * 8;
    #pragma unroll
    for (int cp = 0; cp < 2; cp++) {
        int col = cp * 16 + oc2;
        if (c0 + col < C) {
            uint32_t hw[4];
            #pragma unroll
            for (int i = 0; i < 4; i++) {
                __half2 hp = __floats2half2_rn(t[r8 + 2 * i][col], t[r8 + 2 * i + 1][col]);
                hw[i] = *(uint32_t*)&hp;
            }
            size_t obase = (size_t)(c0 + col) * R + r0 + r8;
            *(uint4*)(out + obase) = make_uint4(hw[0], hw[1], hw[2], hw[3]);
        }
    }
}

// ---------------- embedding: x = emb[tok] + pos, + split ----------------
__global__ void embed_kernel(const int* __restrict__ tok, const float* __restrict__ emb,
                             const float* __restrict__ pos, float* __restrict__ x,
                             __nv_bfloat16* __restrict__ hi, __nv_bfloat16* __restrict__ lo) {
    int i4 = blockIdx.x * 256 + threadIdx.x;
    int e = i4 * 4;
    int s = e >> 10, h = e & 1023;
    float4 ev = *(const float4*)(emb + (size_t)tok[s] * H + h);
    float4 pv = *(const float4*)(pos + e);
    float o0 = ev.x + pv.x, o1 = ev.y + pv.y, o2 = ev.z + pv.z, o3 = ev.w + pv.w;
    *(float4*)(x + e) = make_float4(o0, o1, o2, o3);
    uint2 hv, lv;
    split4(o0, o1, o2, o3, hv, lv);
    *(uint2*)(hi + e) = hv;
    *(uint2*)(lo + e) = lv;
}

// ---------------- fused: M_part = K^T V per (head, seg) + V col sums per 64-row block ----------------
__global__ __launch_bounds__(256)
void ktv_kernel(const float* __restrict__ qkv, float* __restrict__ mp,
                float* __restrict__ part) {
    const int head = blockIdx.x & 15, seg = blockIdx.x >> 4;   // seg 0..15 (128 rows each)
    __shared__ float Ks[64][65];
    __shared__ float Vs[64][65];
    __shared__ float red[4][64];
    const int tid = threadIdx.x;
    const int tr = tid >> 4, tc = tid & 15;
    const int vc = tid & 63, rg = tid >> 6;
    float acc[4][4] = {};
    #pragma unroll
    for (int h2 = 0; h2 < 2; h2++) {
        const int t0 = seg * 128 + h2 * 64;
        for (int i = tid; i < 4096; i += 256) {
            int r = i >> 6, c = i & 63;
            size_t base = (size_t)(t0 + r) * 3072 + head * DH + c;
            Ks[r][c] = qkv[base + 1024];
            Vs[r][c] = qkv[base + 2048];
        }
        __syncthreads();
        #pragma unroll 4
        for (int t = 0; t < 64; t++) {
            float a[4], b[4];
            #pragma unroll
            for (int i = 0; i < 4; i++) a[i] = Ks[t][tr * 4 + i];
            #pragma unroll
            for (int j = 0; j < 4; j++) b[j] = Vs[t][tc * 4 + j];
            #pragma unroll
            for (int i = 0; i < 4; i++)
                #pragma unroll
                for (int j = 0; j < 4; j++)
                    acc[i][j] = fmaf(a[i], b[j], acc[i][j]);
        }
        float csum = 0.f;
        #pragma unroll
        for (int r = 0; r < 16; r++) csum += Vs[rg * 16 + r][vc];
        red[rg][vc] = csum;
        __syncthreads();
        if (tid < 64)
            part[(size_t)(seg * 2 + h2) * 1024 + head * 64 + tid] =
                red[0][tid] + red[1][tid] + red[2][tid] + red[3][tid];
        __syncthreads();
    }
    #pragma unroll
    for (int i = 0; i < 4; i++)
        #pragma unroll
        for (int j = 0; j < 4; j++)
            mp[(size_t)(seg * 16 + head) * 4096 + (tr * 4 + i) * 64 + tc * 4 + j] = acc[i][j];
}

// ---------------- attn = scale*(Q@M) - 1e9*suf(V), fused suffix, emit hi/lo ----------------
#define ATTN_SMEM (50944)
__global__ __launch_bounds__(256)
void attn_combine(const float* __restrict__ qkv, const float* __restrict__ mp,
                  const float* __restrict__ part,
                  __nv_bfloat16* __restrict__ ahi, __nv_bfloat16* __restrict__ alo) {
    extern __shared__ float sm[];
    float (*Qs)[65] = (float(*)[65])sm;
    float (*Ms)[65] = (float(*)[65])(sm + 4160);
    float (*Vs)[65] = (float(*)[65])(sm + 8320);
    float (*red)[64] = (float(*)[64])(sm + 12480);
    const int head = blockIdx.y;
    const int bidx = blockIdx.x;              // 0..31 (64-row blocks)
    const int s0 = bidx * 64;
    const int tid = threadIdx.x;
    for (int i = tid; i < 4096; i += 256) {
        int r = i >> 6, c = i & 63;
        size_t base = (size_t)(s0 + r) * 3072 + head * DH + c;
        Qs[r][c] = qkv[base];
        Vs[r][c] = qkv[base + 2048];
        float mv = 0.f;
        #pragma unroll
        for (int sg = 0; sg < 16; sg++) mv += mp[(size_t)(sg * 16 + head) * 4096 + i];
        Ms[r][c] = mv;
    }
    __syncthreads();

    // convert Vs in place to suffix sums (strictly-after), incl. cross-block tail
    const int vc = tid & 63, q = tid >> 6;
    {
        float qs = 0.f;
        #pragma unroll
        for (int r = 0; r < 16; r++) qs += Vs[q * 16 + r][vc];
        red[q][vc] = qs;
    }
    __syncthreads();
    {
        float run = 0.f;
        for (int b2 = bidx + 1; b2 < 32; b2++)
            run += part[(size_t)b2 * 1024 + head * 64 + vc];
        for (int q2 = q + 1; q2 < 4; q2++) run += red[q2][vc];
        for (int r = q * 16 + 15; r >= q * 16; r--) {
            float tmpv = Vs[r][vc];
            Vs[r][vc] = run;
            run += tmpv;
        }
    }
    __syncthreads();

    const int tr = tid >> 4, tc = tid & 15;
    float acc[4][4] = {};
    #pragma unroll 4
    for (int hp = 0; hp < 64; hp++) {
        float a[4], b[4];
        #pragma unroll
        for (int i = 0; i < 4; i++) a[i] = Qs[tr * 4 + i][hp];
        #pragma unroll
        for (int j = 0; j < 4; j++) b[j] = Ms[hp][tc * 4 + j];
        #pragma unroll
        for (int i = 0; i < 4; i++)
            #pragma unroll
            for (int j = 0; j < 4; j++)
                acc[i][j] = fmaf(a[i], b[j], acc[i][j]);
    }
    #pragma unroll
    for (int i = 0; i < 4; i++) {
        int rr = tr * 4 + i;
        size_t sb = (size_t)(s0 + rr) * 1024 + head * DH + tc * 4;
        float o[4];
        #pragma unroll
        for (int j = 0; j < 4; j++)
            o[j] = 0.125f * acc[i][j] - 1e9f * Vs[rr][tc * 4 + j];
        uint2 hv, lv;
        split4(o[0], o[1], o[2], o[3], hv, lv);
        *(uint2*)(ahi + sb) = hv;
        *(uint2*)(alo + sb) = lv;
    }
}

// ---------------- LayerNorm (+residual) + fused split, warp-shuffle reduce ----------------
template<bool ADD, bool WF32, int OUTK>
__global__ __launch_bounds__(256)
void ln_kernel(const float* __restrict__ t, const float* __restrict__ xin,
               const float* __restrict__ g, const float* __restrict__ b,
               float* __restrict__ outf,
               __nv_bfloat16* __restrict__ hi, __nv_bfloat16* __restrict__ lo,
               __half* __restrict__ outh) {
    const int row = blockIdx.x;
    const int tid = threadIdx.x;
    const int wid = tid >> 5, lane = tid & 31;
    float4 v = *(const float4*)(t + (size_t)row * H + tid * 4);
    __shared__ float wred[8];
    __shared__ float stat[2];

    float s = v.x + v.y + v.z + v.w;
    #pragma unroll
    for (int o = 16; o > 0; o >>= 1) s += __shfl_xor_sync(0xFFFFFFFFu, s, o);
    if (lane == 0) wred[wid] = s;
    __syncthreads();
    if (tid == 0) {
        float tot = 0.f;
        #pragma unroll
        for (int w = 0; w < 8; w++) tot += wred[w];
        stat[0] = tot * (1.0f / H);
    }
    __syncthreads();
    float mean = stat[0];

    float dx = v.x - mean, dy = v.y - mean, dz = v.z - mean, dw = v.w - mean;
    float vs = dx * dx + dy * dy + dz * dz + dw * dw;
    #pragma unroll
    for (int o = 16; o > 0; o >>= 1) vs += __shfl_xor_sync(0xFFFFFFFFu, vs, o);
    if (lane == 0) wred[wid] = vs;
    __syncthreads();
    if (tid == 0) {
        float tot = 0.f;
        #pragma unroll
        for (int w = 0; w < 8; w++) tot += wred[w];
        stat[1] = rsqrtf(tot * (1.0f / H) + 1e-5f);
    }
    __syncthreads();
    float rstd = stat[1];

    int h = tid * 4;
    float4 gv = *(const float4*)(g + h);
    float4 bv = *(const float4*)(b + h);
    float o0 = dx * rstd * gv.x + bv.x;
    float o1 = dy * rstd * gv.y + bv.y;
    float o2 = dz * rstd * gv.z + bv.z;
    float o3 = dw * rstd * gv.w + bv.w;
    if (ADD) {
        float4 xv = *(const float4*)(xin + (size_t)row * H + h);
        o0 += xv.x; o1 += xv.y; o2 += xv.z; o3 += xv.w;
    }
    if (WF32) *(float4*)(outf + (size_t)row * H + h) = make_float4(o0, o1, o2, o3);
    if (OUTK == 0) {
        uint2 hv, lv;
        split4(o0, o1, o2, o3, hv, lv);
        *(uint2*)(hi + (size_t)row * H + h) = hv;
        *(uint2*)(lo + (size_t)row * H + h) = lv;
    } else {
        __half2 h0 = __floats2half2_rn(o0, o1);
        __half2 h1 = __floats2half2_rn(o2, o3);
        *(uint2*)(outh + (size_t)row * H + h) = make_uint2(*(uint32_t*)&h0, *(uint32_t*)&h1);
    }
}

// ---------------- launch ----------------
extern "C" void kernel_launch(void* const* d_in, const int* in_sizes, int n_in,
                              void* d_out, int out_size) {
    const int*   tokens = (const int*)  d_in[0];
    const float* emb    = (const float*)d_in[1];
    const float* pos    = (const float*)d_in[2];
    const float* Wq     = (const float*)d_in[3];
    const float* Wk     = (const float*)d_in[4];
    const float* Wv     = (const float*)d_in[5];
    const float* Wp     = (const float*)d_in[6];
    const float* bp     = (const float*)d_in[7];
    const float* W1     = (const float*)d_in[8];
    const float* b1     = (const float*)d_in[9];
    const float* W2     = (const float*)d_in[10];
    const float* b2     = (const float*)d_in[11];
    const float* ln_g   = (const float*)d_in[12];
    const float* ln_b   = (const float*)d_in[13];
    const float* Wlm    = (const float*)d_in[14];
    const float* blm    = (const float*)d_in[15];
    float* out = (float*)d_out;
    const int Vv = in_sizes[15];

    float *x, *tmp, *res, *qkv, *m, *part, *zb;
    __nv_bfloat16 *ahi, *alo, *bhi, *blo;
    __nv_bfloat16 *btqkv_hi, *btqkv_lo, *btp_hi, *btp_lo;
    __nv_bfloat16 *bt1_hi, *bt1_lo, *bt2_hi, *bt2_lo;
    __half *wlm, *xf16;
    cudaGetSymbolAddress((void**)&x, g_x);       cudaGetSymbolAddress((void**)&tmp, g_tmp);
    cudaGetSymbolAddress((void**)&res, g_res);   cudaGetSymbolAddress((void**)&qkv, g_qkv);
    cudaGetSymbolAddress((void**)&m, g_m);       cudaGetSymbolAddress((void**)&part, g_part);
    cudaGetSymbolAddress((void**)&zb, g_zb);
    cudaGetSymbolAddress((void**)&ahi, g_ahi);   cudaGetSymbolAddress((void**)&alo, g_alo);
    cudaGetSymbolAddress((void**)&bhi, g_bhi);   cudaGetSymbolAddress((void**)&blo, g_blo);
    cudaGetSymbolAddress((void**)&btqkv_hi, g_btqkv_hi);
    cudaGetSymbolAddress((void**)&btqkv_lo, g_btqkv_lo);
    cudaGetSymbolAddress((void**)&btp_hi, g_btp_hi); cudaGetSymbolAddress((void**)&btp_lo, g_btp_lo);
    cudaGetSymbolAddress((void**)&bt1_hi, g_bt1_hi); cudaGetSymbolAddress((void**)&bt1_lo, g_bt1_lo);
    cudaGetSymbolAddress((void**)&bt2_hi, g_bt2_hi); cudaGetSymbolAddress((void**)&bt2_lo, g_bt2_lo);
    cudaGetSymbolAddress((void**)&wlm, g_wlm_f16);   cudaGetSymbolAddress((void**)&xf16, g_xf_f16);

    cudaFuncSetAttribute(gemm_hmma64<0>, cudaFuncAttributeMaxDynamicSharedMemorySize, GEMM64_SMEM);
    cudaFuncSetAttribute(gemm_hmma64<1>, cudaFuncAttributeMaxDynamicSharedMemorySize, GEMM64_SMEM);
    cudaFuncSetAttribute(gemm_f16, cudaFuncAttributeMaxDynamicSharedMemorySize, F16_SMEM);
    cudaFuncSetAttribute(attn_combine, cudaFuncAttributeMaxDynamicSharedMemorySize, ATTN_SMEM);

    dim3 tb(256);
    // idx0: embed
    embed_kernel<<<(S * H) / 1024, 256>>>(tokens, emb, pos, x, ahi, alo);
    // idx1: combined qkv weight transpose (rows 0..1023=Q, 1024..2047=K, 2048..3071=V)
    transpose_split<1><<<dim3(2, 8, 3 * NLAYERS * NH), tb>>>(Wq, Wk, Wv,
                                                             btqkv_hi, btqkv_lo, H, DH);
    // idx2: proj weights
    transpose_split<0><<<dim3(32, 8, NLAYERS), tb>>>(Wp, nullptr, nullptr,
                                                     btp_hi, btp_lo, H, H);
    // idx3: QKV GEMM layer 0 (Q/K columns single-pass double-chunk, V columns bf16x3)
    gemm_hmma64<0><<<dim3(24, 32), 256, GEMM64_SMEM>>>(ahi, alo, btqkv_hi, btqkv_lo,
                                                       zb, qkv, nullptr, nullptr, 3072, H, 2048);
    // remaining weight transposes
    transpose_split<0><<<dim3(128, 8, NLAYERS), tb>>>(W1, nullptr, nullptr, bt1_hi, bt1_lo, H, FF);
    transpose_split<0><<<dim3(32, 32, NLAYERS), tb>>>(W2, nullptr, nullptr, bt2_hi, bt2_lo, FF, H);
    transpose_f16<<<dim3((Vv + 31) / 32, 8), tb>>>(Wlm, wlm, H, Vv);

    for (int l = 0; l < NLAYERS; l++) {
        size_t oQ = (size_t)l * 3072 * H;
        size_t oH = (size_t)l * H * H;
        size_t oF = (size_t)l * H * FF;

        if (l > 0)
            gemm_hmma64<0><<<dim3(24, 32), 256, GEMM64_SMEM>>>(ahi, alo, btqkv_hi + oQ, btqkv_lo + oQ,
                                                               zb, qkv, nullptr, nullptr, 3072, H, 2048);
        ktv_kernel<<<256, 256>>>(qkv, m, part);
        attn_combine<<<dim3(S / 64, NH), 256, ATTN_SMEM>>>(qkv, m, part, ahi, alo);

        gemm_hmma64<0><<<dim3(8, 32), 256, GEMM64_SMEM>>>(ahi, alo, btp_hi + oH, btp_lo + oH,
                                                          bp + (size_t)l * H, tmp, nullptr, nullptr,
                                                          H, H, 0);
        ln_kernel<true, true, 0><<<S, 256>>>(tmp, x, ln_g, ln_b, res, ahi, alo, nullptr);

        gemm_hmma64<1><<<dim3(32, 32), 256, GEMM64_SMEM>>>(ahi, alo, bt1_hi + oF, bt1_lo + oF,
                                                           b1 + (size_t)l * FF, nullptr, bhi, blo,
                                                           FF, H, 0);
        gemm_hmma64<0><<<dim3(8, 32), 256, GEMM64_SMEM>>>(bhi, blo, bt2_hi + oF, bt2_lo + oF,
                                                          b2 + (size_t)l * H, tmp, nullptr, nullptr,
                                                          H, FF, 0);
        ln_kernel<true, true, 0><<<S, 256>>>(tmp, res, ln_g, ln_b, x, ahi, alo, nullptr);
    }

    // final LN -> fp16, LM head in fp16 HMMA
    ln_kernel<false, false, 1><<<S, 256>>>(x, nullptr, ln_g, ln_b, nullptr, nullptr, nullptr, xf16);
    gemm_f16<<<dim3(16, VPAD / 128), 256, F16_SMEM>>>(xf16, wlm, blm, out, Vv, H);
}